// round 1
// baseline (speedup 1.0000x reference)
#include <cuda_runtime.h>

#define N_NODES 8192
#define IN_F    512
#define OUT_F   128
#define ALPHA   0.2f
#define BN_EPS  1e-5f

// ---------------- scratch (device globals; no allocations allowed) ----------------
__device__ __align__(16) float g_ham[IN_F * OUT_F];       // 256 KB
__device__ __align__(16) float g_h[N_NODES * OUT_F];      // 4 MB
__device__ __align__(16) float g_hp[N_NODES * OUT_F];     // 4 MB
__device__ float g_s1[N_NODES];
__device__ float g_s2[N_NODES];
__device__ float g_s2max;
__device__ float g_colsum[OUT_F];
__device__ float g_colsumsq[OUT_F];

// ---------------- helpers ----------------
__device__ __forceinline__ unsigned long long fma2(unsigned long long a,
                                                   unsigned long long b,
                                                   unsigned long long c) {
    unsigned long long d;
    asm("fma.rn.f32x2 %0, %1, %2, %3;" : "=l"(d) : "l"(a), "l"(b), "l"(c));
    return d;
}
__device__ __forceinline__ unsigned long long dup2(float x) {
    unsigned long long d;
    unsigned int u = __float_as_uint(x);
    asm("mov.b64 %0, {%1, %1};" : "=l"(d) : "r"(u));
    return d;
}
__device__ __forceinline__ float2 unpack2(unsigned long long v) {
    float2 f;
    unsigned int lo, hi;
    asm("mov.b64 {%0, %1}, %2;" : "=r"(lo), "=r"(hi) : "l"(v));
    f.x = __uint_as_float(lo);
    f.y = __uint_as_float(hi);
    return f;
}

// ---------------- K1: build hamilton (512x128) + zero BN accumulators ----------------
__global__ void k_ham(const float* __restrict__ W) {
    int idx = blockIdx.x * blockDim.x + threadIdx.x;   // 0..65535
    if (idx < OUT_F) { g_colsum[idx] = 0.f; g_colsumsq[idx] = 0.f; }
    int row = idx >> 7;          // 0..511
    int col = idx & 127;
    int rb = row >> 7, rr = row & 127;
    int cb = col >> 5, cc = col & 31;
    // comp[cb][rb], sign[cb][rb]
    const int   comp_t[4][4] = {{0,1,2,3},{1,0,3,2},{2,3,0,1},{3,2,1,0}};
    const float sign_t[4][4] = {{1.f,-1.f,-1.f,-1.f},
                                {1.f, 1.f,-1.f, 1.f},
                                {1.f, 1.f, 1.f,-1.f},
                                {1.f,-1.f, 1.f, 1.f}};
    g_ham[idx] = sign_t[cb][rb] * W[rr * 128 + comp_t[cb][rb] * 32 + cc];
}

// ---------------- K2: h = input @ hamilton   (8192x512 @ 512x128) ----------------
// 256 blocks x 128 threads; BM=32, BN=128, BK=32; 4x8 microtile.
__global__ void __launch_bounds__(128) k_h(const float* __restrict__ inp) {
    __shared__ __align__(16) float At[32][36];    // At[k][row]
    __shared__ __align__(16) float Bs[32][132];   // Bs[k][col]
    int tid = threadIdx.x;
    int tx = tid & 15, ty = tid >> 4;
    int i0 = blockIdx.x * 32;
    float acc[4][8];
#pragma unroll
    for (int r = 0; r < 4; r++)
#pragma unroll
        for (int c = 0; c < 8; c++) acc[r][c] = 0.f;

    for (int kb = 0; kb < IN_F; kb += 32) {
#pragma unroll
        for (int q = 0; q < 2; q++) {
            int idx = tid * 2 + q;
            int row = idx >> 3, c4 = idx & 7;
            float4 v = *(const float4*)(inp + (size_t)(i0 + row) * IN_F + kb + c4 * 4);
            At[c4 * 4 + 0][row] = v.x;
            At[c4 * 4 + 1][row] = v.y;
            At[c4 * 4 + 2][row] = v.z;
            At[c4 * 4 + 3][row] = v.w;
        }
#pragma unroll
        for (int q = 0; q < 8; q++) {
            int idx = q * 128 + tid;
            int row = idx >> 5, c4 = idx & 31;
            *(float4*)&Bs[row][c4 * 4] = *(const float4*)(g_ham + (kb + row) * OUT_F + c4 * 4);
        }
        __syncthreads();
#pragma unroll
        for (int kk = 0; kk < 32; kk++) {
            float4 a  = *(float4*)&At[kk][ty * 4];
            float4 b0 = *(float4*)&Bs[kk][tx * 8];
            float4 b1 = *(float4*)&Bs[kk][tx * 8 + 4];
            float av[4] = {a.x, a.y, a.z, a.w};
            float bv[8] = {b0.x, b0.y, b0.z, b0.w, b1.x, b1.y, b1.z, b1.w};
#pragma unroll
            for (int r = 0; r < 4; r++)
#pragma unroll
                for (int c = 0; c < 8; c++) acc[r][c] = fmaf(av[r], bv[c], acc[r][c]);
        }
        __syncthreads();
    }
#pragma unroll
    for (int r = 0; r < 4; r++) {
        int gi = i0 + ty * 4 + r;
        float4 o0 = {acc[r][0], acc[r][1], acc[r][2], acc[r][3]};
        float4 o1 = {acc[r][4], acc[r][5], acc[r][6], acc[r][7]};
        *(float4*)(g_h + (size_t)gi * OUT_F + tx * 8)     = o0;
        *(float4*)(g_h + (size_t)gi * OUT_F + tx * 8 + 4) = o1;
    }
}

// ---------------- K3: s1[i] = h[i]·a1, s2[i] = h[i]·a2  (one warp per row) ----------------
__global__ void k_s(const float* __restrict__ a_vec) {
    int warp = (blockIdx.x * blockDim.x + threadIdx.x) >> 5;
    int lane = threadIdx.x & 31;
    if (warp >= N_NODES) return;
    float s1 = 0.f, s2 = 0.f;
#pragma unroll
    for (int q = 0; q < 4; q++) {
        int c = lane + q * 32;
        float hv = g_h[(size_t)warp * OUT_F + c];
        s1 = fmaf(hv, a_vec[c], s1);
        s2 = fmaf(hv, a_vec[OUT_F + c], s2);
    }
#pragma unroll
    for (int off = 16; off > 0; off >>= 1) {
        s1 += __shfl_xor_sync(0xffffffffu, s1, off);
        s2 += __shfl_xor_sync(0xffffffffu, s2, off);
    }
    if (lane == 0) { g_s1[warp] = s1; g_s2[warp] = s2; }
}

// ---------------- K3b: global max of s2 (single block) ----------------
__global__ void k_s2max() {
    __shared__ float red[32];
    int tid = threadIdx.x;            // 256 threads
    float m = -1e30f;
    for (int i = tid; i < N_NODES; i += 256) m = fmaxf(m, g_s2[i]);
#pragma unroll
    for (int off = 16; off > 0; off >>= 1) m = fmaxf(m, __shfl_xor_sync(0xffffffffu, m, off));
    if ((tid & 31) == 0) red[tid >> 5] = m;
    __syncthreads();
    if (tid == 0) {
        float mm = red[0];
        for (int w = 1; w < 8; w++) mm = fmaxf(mm, red[w]);
        g_s2max = mm;
    }
}

// ---------------- K4: fused mask + exp + (P@h) + row-normalize + BN partials ----------------
// 256 blocks x 128 threads; BM=32 rows, BN=128 cols, BK=32 j-chunk.
__global__ void __launch_bounds__(128) k_attn(const int* __restrict__ adj) {
    __shared__ __align__(16) float Pt[32][36];    // Pt[kk][row]
    __shared__ __align__(16) float Hs[32][132];   // Hs[kk][col]
    __shared__ float zr[32];
    int tid = threadIdx.x;
    int tx = tid & 15, ty = tid >> 4;
    int i0 = blockIdx.x * 32;

    if (tid < 32) zr[tid] = 0.f;
    float s2max = g_s2max;

    // P-phase per-thread row constants (2 rows per thread, fixed across chunks)
    int   prow[2];
    float ps1[2], pm[2];
#pragma unroll
    for (int q = 0; q < 2; q++) {
        int idx = tid * 2 + q;
        prow[q] = idx >> 3;
        float s1v = g_s1[i0 + prow[q]];
        ps1[q] = s1v;
        float m = s1v + s2max;
        pm[q] = (m > 0.f) ? m : ALPHA * m;
    }

    unsigned long long acc[4][4];
#pragma unroll
    for (int r = 0; r < 4; r++)
#pragma unroll
        for (int cp = 0; cp < 4; cp++) acc[r][cp] = 0ull;

    __syncthreads();

    for (int jb = 0; jb < N_NODES; jb += 32) {
        // H tile: 32 x 128
#pragma unroll
        for (int q = 0; q < 8; q++) {
            int idx = q * 128 + tid;
            int row = idx >> 5, c4 = idx & 31;
            *(float4*)&Hs[row][c4 * 4] = *(const float4*)(g_h + (size_t)(jb + row) * OUT_F + c4 * 4);
        }
        // P tile: 32 rows x 32 j; each thread handles 2 (row, 4-j) groups
#pragma unroll
        for (int q = 0; q < 2; q++) {
            int idx = tid * 2 + q;
            int row = prow[q];
            int c4 = idx & 7;
            const int4 av = *(const int4*)(adj + (size_t)(i0 + row) * N_NODES + jb + c4 * 4);
            float s1v = ps1[q], mv = pm[q];
            int jbase = jb + c4 * 4;
            float zp = 0.f;
            {
                float e = s1v + g_s2[jbase + 0]; e = (e > 0.f) ? e : ALPHA * e;
                float p = (av.x > 0) ? __expf(e - mv) : 0.f;
                Pt[c4 * 4 + 0][row] = p; zp += p;
            }
            {
                float e = s1v + g_s2[jbase + 1]; e = (e > 0.f) ? e : ALPHA * e;
                float p = (av.y > 0) ? __expf(e - mv) : 0.f;
                Pt[c4 * 4 + 1][row] = p; zp += p;
            }
            {
                float e = s1v + g_s2[jbase + 2]; e = (e > 0.f) ? e : ALPHA * e;
                float p = (av.z > 0) ? __expf(e - mv) : 0.f;
                Pt[c4 * 4 + 2][row] = p; zp += p;
            }
            {
                float e = s1v + g_s2[jbase + 3]; e = (e > 0.f) ? e : ALPHA * e;
                float p = (av.w > 0) ? __expf(e - mv) : 0.f;
                Pt[c4 * 4 + 3][row] = p; zp += p;
            }
            atomicAdd(&zr[row], zp);
        }
        __syncthreads();

        // GEMM: 32 kk, f32x2 packed FMAs
#pragma unroll
        for (int kk = 0; kk < 32; kk++) {
            float4 pv = *(float4*)&Pt[kk][ty * 4];
            ulonglong2 b01 = *(ulonglong2*)&Hs[kk][tx * 8];
            ulonglong2 b23 = *(ulonglong2*)&Hs[kk][tx * 8 + 4];
            unsigned long long bb[4] = {b01.x, b01.y, b23.x, b23.y};
            float pr[4] = {pv.x, pv.y, pv.z, pv.w};
#pragma unroll
            for (int r = 0; r < 4; r++) {
                unsigned long long pd = dup2(pr[r]);
#pragma unroll
                for (int cp = 0; cp < 4; cp++) acc[r][cp] = fma2(pd, bb[cp], acc[r][cp]);
            }
        }
        __syncthreads();
    }

    // finalize: normalize by z, write h', accumulate BN column partials
    float colp[8], colq[8];
#pragma unroll
    for (int c = 0; c < 8; c++) { colp[c] = 0.f; colq[c] = 0.f; }

#pragma unroll
    for (int r = 0; r < 4; r++) {
        int row = ty * 4 + r;
        float invz = 1.0f / zr[row];
        float o[8];
#pragma unroll
        for (int cp = 0; cp < 4; cp++) {
            float2 v = unpack2(acc[r][cp]);
            o[2 * cp]     = v.x * invz;
            o[2 * cp + 1] = v.y * invz;
        }
        int gi = i0 + row;
        float4 o0 = {o[0], o[1], o[2], o[3]};
        float4 o1 = {o[4], o[5], o[6], o[7]};
        *(float4*)(g_hp + (size_t)gi * OUT_F + tx * 8)     = o0;
        *(float4*)(g_hp + (size_t)gi * OUT_F + tx * 8 + 4) = o1;
#pragma unroll
        for (int c = 0; c < 8; c++) {
            colp[c] += o[c];
            colq[c] = fmaf(o[c], o[c], colq[c]);
        }
    }
#pragma unroll
    for (int c = 0; c < 8; c++) {
        atomicAdd(&g_colsum[tx * 8 + c],   colp[c]);
        atomicAdd(&g_colsumsq[tx * 8 + c], colq[c]);
    }
}

// ---------------- K5: BatchNorm (population stats over rows) + ELU ----------------
__global__ void k_bn(const float* __restrict__ gamma, const float* __restrict__ beta,
                     float* __restrict__ out) {
    int idx = blockIdx.x * blockDim.x + threadIdx.x;   // 0 .. 8192*128-1
    int col = idx & 127;
    const float invN = 1.0f / (float)N_NODES;
    float mean = g_colsum[col] * invN;
    float var  = g_colsumsq[col] * invN - mean * mean;
    float rstd = rsqrtf(var + BN_EPS);
    float v = (g_hp[idx] - mean) * rstd * gamma[col] + beta[col];
    out[idx] = (v > 0.f) ? v : expm1f(v);
}

// ---------------- launch ----------------
extern "C" void kernel_launch(void* const* d_in, const int* in_sizes, int n_in,
                              void* d_out, int out_size) {
    (void)in_sizes; (void)n_in; (void)out_size;
    const float* inp   = (const float*)d_in[0];
    const int*   adj   = (const int*)  d_in[1];
    const float* W     = (const float*)d_in[2];
    const float* a_vec = (const float*)d_in[3];
    const float* gamma = (const float*)d_in[4];
    const float* beta  = (const float*)d_in[5];
    float* out = (float*)d_out;

    k_ham  <<<256, 256>>>(W);
    k_h    <<<256, 128>>>(inp);
    k_s    <<<1024, 256>>>(a_vec);
    k_s2max<<<1, 256>>>();
    k_attn <<<256, 128>>>(adj);
    k_bn   <<<4096, 256>>>(gamma, beta, out);
}

// round 3
// speedup vs baseline: 2.3236x; 2.3236x over previous
#include <cuda_runtime.h>
#include <cstdint>

#define N_NODES 8192
#define IN_F    512
#define OUT_F   128
#define ALPHA   0.2f
#define BN_EPS  1e-5f

// ---------------- scratch (device globals; no allocations allowed) ----------------
__device__ __align__(16) float g_ham[IN_F * OUT_F];        // 256 KB
__device__ __align__(16) float g_h[N_NODES * OUT_F];       // 4 MB fp32 (for k_s)
__device__ __align__(16) float g_hT32[OUT_F * N_NODES];    // 4 MB tf32-rounded, [c][j]
__device__ __align__(16) float g_hp[N_NODES * OUT_F];      // 4 MB
__device__ float  g_s1[N_NODES];
__device__ float  g_s2[N_NODES];
__device__ unsigned int g_s2max_u;
__device__ __align__(16) float2 g_A12[N_NODES];            // {exp(s1-m), exp(0.2 s1-m)}
__device__ __align__(16) float2 g_E12[N_NODES];            // {exp(s2),   exp(0.2 s2)}
__device__ float g_colsum[OUT_F];
__device__ float g_colsumsq[OUT_F];

// ---------------- helpers ----------------
__device__ __forceinline__ unsigned long long fma2(unsigned long long a,
                                                   unsigned long long b,
                                                   unsigned long long c) {
    unsigned long long d;
    asm("fma.rn.f32x2 %0, %1, %2, %3;" : "=l"(d) : "l"(a), "l"(b), "l"(c));
    return d;
}
__device__ __forceinline__ unsigned long long dup2(float x) {
    unsigned long long d;
    unsigned int u = __float_as_uint(x);
    asm("mov.b64 %0, {%1, %1};" : "=l"(d) : "r"(u));
    return d;
}
__device__ __forceinline__ float2 unpack2(unsigned long long v) {
    float2 f;
    unsigned int lo, hi;
    asm("mov.b64 {%0, %1}, %2;" : "=r"(lo), "=r"(hi) : "l"(v));
    f.x = __uint_as_float(lo);
    f.y = __uint_as_float(hi);
    return f;
}
__device__ __forceinline__ float tf32r(float x) {   // round-to-nearest tf32 in fp32 container
    uint32_t o;
    asm("cvt.rna.tf32.f32 %0, %1;" : "=r"(o) : "f"(x));
    return __uint_as_float(o);
}
// m16n8k8 tf32 mma
__device__ __forceinline__ void mma8(float* c, const uint32_t* a, const uint32_t* b) {
    asm volatile(
        "mma.sync.aligned.m16n8k8.row.col.f32.tf32.tf32.f32 "
        "{%0,%1,%2,%3}, {%4,%5,%6,%7}, {%8,%9}, {%0,%1,%2,%3};"
        : "+f"(c[0]), "+f"(c[1]), "+f"(c[2]), "+f"(c[3])
        : "r"(a[0]), "r"(a[1]), "r"(a[2]), "r"(a[3]), "r"(b[0]), "r"(b[1]));
}

// ---------------- K1: hamilton + zero accumulators ----------------
__global__ void k_ham(const float* __restrict__ W) {
    int idx = blockIdx.x * blockDim.x + threadIdx.x;   // 0..65535
    if (idx < OUT_F) { g_colsum[idx] = 0.f; g_colsumsq[idx] = 0.f; }
    if (idx == 0) g_s2max_u = 0x007FFFFFu;             // encoded -inf
    int row = idx >> 7;
    int col = idx & 127;
    int rb = row >> 7, rr = row & 127;
    int cb = col >> 5, cc = col & 31;
    const int   comp_t[4][4] = {{0,1,2,3},{1,0,3,2},{2,3,0,1},{3,2,1,0}};
    const float sign_t[4][4] = {{1.f,-1.f,-1.f,-1.f},
                                {1.f, 1.f,-1.f, 1.f},
                                {1.f, 1.f, 1.f,-1.f},
                                {1.f,-1.f, 1.f, 1.f}};
    g_ham[idx] = sign_t[cb][rb] * W[rr * 128 + comp_t[cb][rb] * 32 + cc];
}

// ---------------- K2: h = input @ hamilton (fp32), + transposed tf32 copy ----------------
__global__ void __launch_bounds__(128) k_h(const float* __restrict__ inp) {
    __shared__ __align__(16) float At[32][36];
    __shared__ __align__(16) float Bs[32][132];
    int tid = threadIdx.x;
    int tx = tid & 15, ty = tid >> 4;
    int i0 = blockIdx.x * 32;
    unsigned long long acc[4][4];
#pragma unroll
    for (int r = 0; r < 4; r++)
#pragma unroll
        for (int cp = 0; cp < 4; cp++) acc[r][cp] = 0ull;

    for (int kb = 0; kb < IN_F; kb += 32) {
#pragma unroll
        for (int q = 0; q < 2; q++) {
            int idx = tid * 2 + q;
            int row = idx >> 3, c4 = idx & 7;
            float4 v = *(const float4*)(inp + (size_t)(i0 + row) * IN_F + kb + c4 * 4);
            At[c4 * 4 + 0][row] = v.x;
            At[c4 * 4 + 1][row] = v.y;
            At[c4 * 4 + 2][row] = v.z;
            At[c4 * 4 + 3][row] = v.w;
        }
#pragma unroll
        for (int q = 0; q < 8; q++) {
            int idx = q * 128 + tid;
            int row = idx >> 5, c4 = idx & 31;
            *(float4*)&Bs[row][c4 * 4] = *(const float4*)(g_ham + (kb + row) * OUT_F + c4 * 4);
        }
        __syncthreads();
#pragma unroll
        for (int kk = 0; kk < 32; kk++) {
            float4 a = *(float4*)&At[kk][ty * 4];
            ulonglong2 b01 = *(ulonglong2*)&Bs[kk][tx * 8];
            ulonglong2 b23 = *(ulonglong2*)&Bs[kk][tx * 8 + 4];
            unsigned long long bb[4] = {b01.x, b01.y, b23.x, b23.y};
            float av[4] = {a.x, a.y, a.z, a.w};
#pragma unroll
            for (int r = 0; r < 4; r++) {
                unsigned long long pd = dup2(av[r]);
#pragma unroll
                for (int cp = 0; cp < 4; cp++) acc[r][cp] = fma2(pd, bb[cp], acc[r][cp]);
            }
        }
        __syncthreads();
    }
    float o[4][8];
#pragma unroll
    for (int r = 0; r < 4; r++)
#pragma unroll
        for (int cp = 0; cp < 4; cp++) {
            float2 v = unpack2(acc[r][cp]);
            o[r][2 * cp] = v.x; o[r][2 * cp + 1] = v.y;
        }
#pragma unroll
    for (int r = 0; r < 4; r++) {
        int gi = i0 + ty * 4 + r;
        float4 o0 = {o[r][0], o[r][1], o[r][2], o[r][3]};
        float4 o1 = {o[r][4], o[r][5], o[r][6], o[r][7]};
        *(float4*)(g_h + (size_t)gi * OUT_F + tx * 8)     = o0;
        *(float4*)(g_h + (size_t)gi * OUT_F + tx * 8 + 4) = o1;
    }
#pragma unroll
    for (int c = 0; c < 8; c++) {
        float4 t = {tf32r(o[0][c]), tf32r(o[1][c]), tf32r(o[2][c]), tf32r(o[3][c])};
        *(float4*)(g_hT32 + (size_t)(tx * 8 + c) * N_NODES + i0 + ty * 4) = t;
    }
}

// ---------------- K3: s1/s2 per row + global s2 max ----------------
__global__ void k_s(const float* __restrict__ a_vec) {
    __shared__ float s2b[8];
    int tid = threadIdx.x;
    int warp = (blockIdx.x * blockDim.x + tid) >> 5;
    int lane = tid & 31;
    float s1 = 0.f, s2 = 0.f;
#pragma unroll
    for (int q = 0; q < 4; q++) {
        int c = lane + q * 32;
        float hv = g_h[(size_t)warp * OUT_F + c];
        s1 = fmaf(hv, a_vec[c], s1);
        s2 = fmaf(hv, a_vec[OUT_F + c], s2);
    }
#pragma unroll
    for (int off = 16; off > 0; off >>= 1) {
        s1 += __shfl_xor_sync(0xffffffffu, s1, off);
        s2 += __shfl_xor_sync(0xffffffffu, s2, off);
    }
    if (lane == 0) {
        g_s1[warp] = s1; g_s2[warp] = s2;
        s2b[tid >> 5] = s2;
    }
    __syncthreads();
    if (tid == 0) {
        float m = s2b[0];
#pragma unroll
        for (int w = 1; w < 8; w++) m = fmaxf(m, s2b[w]);
        uint32_t u = __float_as_uint(m);
        u = (u & 0x80000000u) ? ~u : (u | 0x80000000u);
        atomicMax(&g_s2max_u, u);
    }
}

// ---------------- K3b: per-node exp factors ----------------
__global__ void k_prep() {
    int i = blockIdx.x * blockDim.x + threadIdx.x;    // 0..8191
    uint32_t mu = g_s2max_u;
    float s2max = (mu & 0x80000000u) ? __uint_as_float(mu ^ 0x80000000u)
                                     : __uint_as_float(~mu);
    float s1 = g_s1[i], s2 = g_s2[i];
    float m = s1 + s2max;
    m = (m > 0.f) ? m : ALPHA * m;
    g_A12[i] = make_float2(__expf(s1 - m), __expf(ALPHA * s1 - m));
    g_E12[i] = make_float2(__expf(s2), __expf(ALPHA * s2));
}

// ---------------- K4: fused attention via mma.sync tf32 ----------------
// 128 CTAs x 256 thr (8 warps in 2x4). BM=64, BN=128, BK=64, double-buffered.
#define PT_F 4352          // 64*68 floats per Pt buffer
#define HS_F 8704          // 128*68 floats per Hst buffer
__global__ void __launch_bounds__(256, 1) k_attn(const int* __restrict__ adj) {
    extern __shared__ __align__(16) float smem[];
    float* Pt  = smem;                         // 2 buffers
    float* Hst = smem + 2 * PT_F;              // 2 buffers (c-major)
    float* zsh = smem + 2 * PT_F + 2 * HS_F;   // 64 floats

    const int tid  = threadIdx.x;
    const int wid  = tid >> 5;
    const int lane = tid & 31;
    const int gid  = lane >> 2;
    const int t4   = lane & 3;
    const int i0   = blockIdx.x * 64;
    const int m0   = (wid >> 2) * 32;          // warp row offset (0/32)
    const int n0   = (wid & 3) * 32;           // warp col offset (0/32/64/96)

    if (tid < 64) zsh[tid] = 0.f;

    // P-build constants: row fixed per thread
    const int row = tid >> 2;
    const int jl0 = (tid & 3) * 16;
    const float2 a12 = g_A12[i0 + row];
    const float A1 = a12.x, A2 = a12.y;
    const int* arow = adj + (size_t)(i0 + row) * N_NODES + jl0;
    // H staging: thread covers c = tid>>1, 32 cols
    const int hc = tid >> 1;
    const int hh = (tid & 1) * 32;
    const float* hsrc = g_hT32 + (size_t)hc * N_NODES + hh;

    float acc[2][4][4];
#pragma unroll
    for (int mb = 0; mb < 2; mb++)
#pragma unroll
        for (int nb = 0; nb < 4; nb++)
#pragma unroll
            for (int q = 0; q < 4; q++) acc[mb][nb][q] = 0.f;

    float zacc = 0.f;

    // preload adj for chunk 0
    int4 av[4];
#pragma unroll
    for (int g = 0; g < 4; g++) av[g] = *(const int4*)(arow + g * 4);

    for (int cc = 0; cc < 128; cc++) {
        const int jb = cc << 6;
        const int p = cc & 1;
        float* PtB  = Pt + p * PT_F;
        float* HstB = Hst + p * HS_F;

        // ---- build P tile ----
#pragma unroll
        for (int g = 0; g < 4; g++) {
            int jj = jb + jl0 + g * 4;
            float4 ea = *(const float4*)(&g_E12[jj]);       // E12[j], E12[j+1]
            float4 eb = *(const float4*)(&g_E12[jj + 2]);   // E12[j+2], E12[j+3]
            int4 a = av[g];
            float q0 = fmaxf(A1 * ea.x, A2 * ea.y);
            float q1 = fmaxf(A1 * ea.z, A2 * ea.w);
            float q2 = fmaxf(A1 * eb.x, A2 * eb.y);
            float q3 = fmaxf(A1 * eb.z, A2 * eb.w);
            float4 pv;
            pv.x = (a.x > 0) ? tf32r(q0) : 0.f;
            pv.y = (a.y > 0) ? tf32r(q1) : 0.f;
            pv.z = (a.z > 0) ? tf32r(q2) : 0.f;
            pv.w = (a.w > 0) ? tf32r(q3) : 0.f;
            zacc += (pv.x + pv.y) + (pv.z + pv.w);
            *(float4*)(PtB + row * 68 + jl0 + g * 4) = pv;
        }
        // ---- stage H tile (c-major) ----
        {
            const float* s = hsrc + jb;
            float* d = HstB + hc * 68 + hh;
#pragma unroll
            for (int q = 0; q < 8; q++)
                *(float4*)(d + q * 4) = *(const float4*)(s + q * 4);
        }
        // ---- prefetch next adj ----
        {
            int njb = ((cc + 1) & 127) << 6;
#pragma unroll
            for (int g = 0; g < 4; g++) av[g] = *(const int4*)(arow + njb + g * 4);
        }
        __syncthreads();

        // ---- mma phase ----
        const uint32_t* Pu = (const uint32_t*)PtB;
        const uint32_t* Hu = (const uint32_t*)HstB;
#pragma unroll
        for (int ks = 0; ks < 8; ks++) {
            const int k0 = ks * 8 + t4;
            uint32_t af[2][4], bf[4][2];
#pragma unroll
            for (int mb = 0; mb < 2; mb++) {
                int r0 = (m0 + mb * 16 + gid) * 68 + k0;
                af[mb][0] = Pu[r0];
                af[mb][1] = Pu[r0 + 8 * 68];
                af[mb][2] = Pu[r0 + 4];
                af[mb][3] = Pu[r0 + 8 * 68 + 4];
            }
#pragma unroll
            for (int nb = 0; nb < 4; nb++) {
                int c0 = (n0 + nb * 8 + gid) * 68 + k0;
                bf[nb][0] = Hu[c0];
                bf[nb][1] = Hu[c0 + 4];
            }
#pragma unroll
            for (int mb = 0; mb < 2; mb++)
#pragma unroll
                for (int nb = 0; nb < 4; nb++)
                    mma8(acc[mb][nb], af[mb], bf[nb]);
        }
        __syncthreads();
    }

    // ---- epilogue: z normalize + write ----
    atomicAdd(&zsh[row], zacc);
    __syncthreads();
#pragma unroll
    for (int mb = 0; mb < 2; mb++) {
        int r0 = m0 + mb * 16 + gid;
        float rz0 = 1.0f / zsh[r0];
        float rz1 = 1.0f / zsh[r0 + 8];
#pragma unroll
        for (int nb = 0; nb < 4; nb++) {
            int col = n0 + nb * 8 + t4 * 2;
            float2 v0 = {acc[mb][nb][0] * rz0, acc[mb][nb][1] * rz0};
            float2 v1 = {acc[mb][nb][2] * rz1, acc[mb][nb][3] * rz1};
            *(float2*)(g_hp + (size_t)(i0 + r0) * OUT_F + col)     = v0;
            *(float2*)(g_hp + (size_t)(i0 + r0 + 8) * OUT_F + col) = v1;
        }
    }
}

// ---------------- K5: BN column stats ----------------
__global__ void k_stats() {
    int col = threadIdx.x & 127;
    int h = threadIdx.x >> 7;
    int r0 = blockIdx.x * 128;
    float s = 0.f, q = 0.f;
    for (int r = h; r < 128; r += 2) {
        float v = g_hp[(size_t)(r0 + r) * OUT_F + col];
        s += v; q = fmaf(v, v, q);
    }
    atomicAdd(&g_colsum[col], s);
    atomicAdd(&g_colsumsq[col], q);
}

// ---------------- K6: BatchNorm + ELU ----------------
__global__ void k_bn(const float* __restrict__ gamma, const float* __restrict__ beta,
                     float* __restrict__ out) {
    int idx = blockIdx.x * blockDim.x + threadIdx.x;
    int col = idx & 127;
    const float invN = 1.0f / (float)N_NODES;
    float mean = g_colsum[col] * invN;
    float var  = g_colsumsq[col] * invN - mean * mean;
    float rstd = rsqrtf(var + BN_EPS);
    float v = (g_hp[idx] - mean) * rstd * gamma[col] + beta[col];
    out[idx] = (v > 0.f) ? v : expm1f(v);
}

// ---------------- launch ----------------
extern "C" void kernel_launch(void* const* d_in, const int* in_sizes, int n_in,
                              void* d_out, int out_size) {
    (void)in_sizes; (void)n_in; (void)out_size;
    const float* inp   = (const float*)d_in[0];
    const int*   adj   = (const int*)  d_in[1];
    const float* W     = (const float*)d_in[2];
    const float* a_vec = (const float*)d_in[3];
    const float* gamma = (const float*)d_in[4];
    const float* beta  = (const float*)d_in[5];
    float* out = (float*)d_out;

    const int ATTN_SMEM = (2 * PT_F + 2 * HS_F + 64) * 4;   // 104960 B
    static int smem_set = 0;
    if (!smem_set) {
        cudaFuncSetAttribute(k_attn, cudaFuncAttributeMaxDynamicSharedMemorySize, ATTN_SMEM);
        smem_set = 1;
    }

    k_ham  <<<256, 256>>>(W);
    k_h    <<<256, 128>>>(inp);
    k_s    <<<1024, 256>>>(a_vec);
    k_prep <<<32, 256>>>();
    k_attn <<<128, 256, ATTN_SMEM>>>(adj);
    k_stats<<<64, 256>>>();
    k_bn   <<<4096, 256>>>(gamma, beta, out);
}

// round 4
// speedup vs baseline: 3.4081x; 1.4667x over previous
#include <cuda_runtime.h>
#include <cstdint>

#define N_NODES 8192
#define IN_F    512
#define OUT_F   128
#define ALPHA   0.2f
#define BN_EPS  1e-5f

// ---------------- scratch (device globals; no allocations allowed) ----------------
__device__ __align__(16) float g_ham[IN_F * OUT_F];        // 256 KB
__device__ __align__(16) float g_h[N_NODES * OUT_F];       // 4 MB fp32 (for k_s)
__device__ __align__(16) float g_hT32[OUT_F * N_NODES];    // 4 MB tf32-rounded, [c][j]
__device__ __align__(16) float g_hp[N_NODES * OUT_F];      // 4 MB
__device__ float  g_s1[N_NODES];
__device__ float  g_s2[N_NODES];
__device__ unsigned int g_s2max_u;
__device__ __align__(16) float2 g_A12[N_NODES];            // {exp(s1-m), exp(0.2 s1-m)}
__device__ __align__(16) float2 g_E12[N_NODES];            // {exp(s2),   exp(0.2 s2)}
__device__ float g_colsum[OUT_F];
__device__ float g_colsumsq[OUT_F];

// ---------------- helpers ----------------
__device__ __forceinline__ unsigned long long fma2(unsigned long long a,
                                                   unsigned long long b,
                                                   unsigned long long c) {
    unsigned long long d;
    asm("fma.rn.f32x2 %0, %1, %2, %3;" : "=l"(d) : "l"(a), "l"(b), "l"(c));
    return d;
}
__device__ __forceinline__ unsigned long long dup2(float x) {
    unsigned long long d;
    unsigned int u = __float_as_uint(x);
    asm("mov.b64 %0, {%1, %1};" : "=l"(d) : "r"(u));
    return d;
}
__device__ __forceinline__ float2 unpack2(unsigned long long v) {
    float2 f;
    unsigned int lo, hi;
    asm("mov.b64 {%0, %1}, %2;" : "=r"(lo), "=r"(hi) : "l"(v));
    f.x = __uint_as_float(lo);
    f.y = __uint_as_float(hi);
    return f;
}
__device__ __forceinline__ float tf32r(float x) {
    uint32_t o;
    asm("cvt.rna.tf32.f32 %0, %1;" : "=r"(o) : "f"(x));
    return __uint_as_float(o);
}
__device__ __forceinline__ uint32_t smem_u32(const void* p) {
    uint32_t a;
    asm("{ .reg .u64 t; cvta.to.shared.u64 t, %1; cvt.u32.u64 %0, t; }" : "=r"(a) : "l"(p));
    return a;
}
__device__ __forceinline__ void cp16(uint32_t dst, const void* src) {
    asm volatile("cp.async.cg.shared.global [%0], [%1], 16;" :: "r"(dst), "l"(src) : "memory");
}
__device__ __forceinline__ void cp_commit() {
    asm volatile("cp.async.commit_group;" ::: "memory");
}
__device__ __forceinline__ void cp_wait0() {
    asm volatile("cp.async.wait_group 0;" ::: "memory");
}
// m16n8k8 tf32 mma
__device__ __forceinline__ void mma8(float* c, const uint32_t* a, const uint32_t* b) {
    asm volatile(
        "mma.sync.aligned.m16n8k8.row.col.f32.tf32.tf32.f32 "
        "{%0,%1,%2,%3}, {%4,%5,%6,%7}, {%8,%9}, {%0,%1,%2,%3};"
        : "+f"(c[0]), "+f"(c[1]), "+f"(c[2]), "+f"(c[3])
        : "r"(a[0]), "r"(a[1]), "r"(a[2]), "r"(a[3]), "r"(b[0]), "r"(b[1]));
}

// ---------------- K1: hamilton + zero accumulators ----------------
__global__ void k_ham(const float* __restrict__ W) {
    int idx = blockIdx.x * blockDim.x + threadIdx.x;
    if (idx < OUT_F) { g_colsum[idx] = 0.f; g_colsumsq[idx] = 0.f; }
    if (idx == 0) g_s2max_u = 0x007FFFFFu;
    int row = idx >> 7;
    int col = idx & 127;
    int rb = row >> 7, rr = row & 127;
    int cb = col >> 5, cc = col & 31;
    const int   comp_t[4][4] = {{0,1,2,3},{1,0,3,2},{2,3,0,1},{3,2,1,0}};
    const float sign_t[4][4] = {{1.f,-1.f,-1.f,-1.f},
                                {1.f, 1.f,-1.f, 1.f},
                                {1.f, 1.f, 1.f,-1.f},
                                {1.f,-1.f, 1.f, 1.f}};
    g_ham[idx] = sign_t[cb][rb] * W[rr * 128 + comp_t[cb][rb] * 32 + cc];
}

// ---------------- K2: h = input @ hamilton (fp32), + transposed tf32 copy ----------------
__global__ void __launch_bounds__(128) k_h(const float* __restrict__ inp) {
    __shared__ __align__(16) float At[32][36];
    __shared__ __align__(16) float Bs[32][132];
    int tid = threadIdx.x;
    int tx = tid & 15, ty = tid >> 4;
    int i0 = blockIdx.x * 32;
    unsigned long long acc[4][4];
#pragma unroll
    for (int r = 0; r < 4; r++)
#pragma unroll
        for (int cp = 0; cp < 4; cp++) acc[r][cp] = 0ull;

    for (int kb = 0; kb < IN_F; kb += 32) {
#pragma unroll
        for (int q = 0; q < 2; q++) {
            int idx = tid * 2 + q;
            int row = idx >> 3, c4 = idx & 7;
            float4 v = *(const float4*)(inp + (size_t)(i0 + row) * IN_F + kb + c4 * 4);
            At[c4 * 4 + 0][row] = v.x;
            At[c4 * 4 + 1][row] = v.y;
            At[c4 * 4 + 2][row] = v.z;
            At[c4 * 4 + 3][row] = v.w;
        }
#pragma unroll
        for (int q = 0; q < 8; q++) {
            int idx = q * 128 + tid;
            int row = idx >> 5, c4 = idx & 31;
            *(float4*)&Bs[row][c4 * 4] = *(const float4*)(g_ham + (kb + row) * OUT_F + c4 * 4);
        }
        __syncthreads();
#pragma unroll
        for (int kk = 0; kk < 32; kk++) {
            float4 a = *(float4*)&At[kk][ty * 4];
            ulonglong2 b01 = *(ulonglong2*)&Bs[kk][tx * 8];
            ulonglong2 b23 = *(ulonglong2*)&Bs[kk][tx * 8 + 4];
            unsigned long long bb[4] = {b01.x, b01.y, b23.x, b23.y};
            float av[4] = {a.x, a.y, a.z, a.w};
#pragma unroll
            for (int r = 0; r < 4; r++) {
                unsigned long long pd = dup2(av[r]);
#pragma unroll
                for (int cp = 0; cp < 4; cp++) acc[r][cp] = fma2(pd, bb[cp], acc[r][cp]);
            }
        }
        __syncthreads();
    }
    float o[4][8];
#pragma unroll
    for (int r = 0; r < 4; r++)
#pragma unroll
        for (int cp = 0; cp < 4; cp++) {
            float2 v = unpack2(acc[r][cp]);
            o[r][2 * cp] = v.x; o[r][2 * cp + 1] = v.y;
        }
#pragma unroll
    for (int r = 0; r < 4; r++) {
        int gi = i0 + ty * 4 + r;
        float4 o0 = {o[r][0], o[r][1], o[r][2], o[r][3]};
        float4 o1 = {o[r][4], o[r][5], o[r][6], o[r][7]};
        *(float4*)(g_h + (size_t)gi * OUT_F + tx * 8)     = o0;
        *(float4*)(g_h + (size_t)gi * OUT_F + tx * 8 + 4) = o1;
    }
#pragma unroll
    for (int c = 0; c < 8; c++) {
        float4 t = {tf32r(o[0][c]), tf32r(o[1][c]), tf32r(o[2][c]), tf32r(o[3][c])};
        *(float4*)(g_hT32 + (size_t)(tx * 8 + c) * N_NODES + i0 + ty * 4) = t;
    }
}

// ---------------- K3: s1/s2 per row + global s2 max ----------------
__global__ void k_s(const float* __restrict__ a_vec) {
    __shared__ float s2b[8];
    int tid = threadIdx.x;
    int warp = (blockIdx.x * blockDim.x + tid) >> 5;
    int lane = tid & 31;
    float s1 = 0.f, s2 = 0.f;
#pragma unroll
    for (int q = 0; q < 4; q++) {
        int c = lane + q * 32;
        float hv = g_h[(size_t)warp * OUT_F + c];
        s1 = fmaf(hv, a_vec[c], s1);
        s2 = fmaf(hv, a_vec[OUT_F + c], s2);
    }
#pragma unroll
    for (int off = 16; off > 0; off >>= 1) {
        s1 += __shfl_xor_sync(0xffffffffu, s1, off);
        s2 += __shfl_xor_sync(0xffffffffu, s2, off);
    }
    if (lane == 0) {
        g_s1[warp] = s1; g_s2[warp] = s2;
        s2b[tid >> 5] = s2;
    }
    __syncthreads();
    if (tid == 0) {
        float m = s2b[0];
#pragma unroll
        for (int w = 1; w < 8; w++) m = fmaxf(m, s2b[w]);
        uint32_t u = __float_as_uint(m);
        u = (u & 0x80000000u) ? ~u : (u | 0x80000000u);
        atomicMax(&g_s2max_u, u);
    }
}

// ---------------- K3b: per-node exp factors ----------------
__global__ void k_prep() {
    int i = blockIdx.x * blockDim.x + threadIdx.x;
    uint32_t mu = g_s2max_u;
    float s2max = (mu & 0x80000000u) ? __uint_as_float(mu ^ 0x80000000u)
                                     : __uint_as_float(~mu);
    float s1 = g_s1[i], s2 = g_s2[i];
    float m = s1 + s2max;
    m = (m > 0.f) ? m : ALPHA * m;
    g_A12[i] = make_float2(__expf(s1 - m), __expf(ALPHA * s1 - m));
    g_E12[i] = make_float2(__expf(s2), __expf(ALPHA * s2));
}

// ---------------- K4: fused attention via mma.sync tf32, software-pipelined ----------------
// 128 CTAs x 512 thr (16 warps in 4x4). BM=64, BN=128, BK=64, double-buffered.
#define PT_F 4352          // 64*68
#define HS_F 8704          // 128*68
__global__ void __launch_bounds__(512, 1) k_attn(const int* __restrict__ adj) {
    extern __shared__ __align__(16) float smem[];
    float* Pt  = smem;                         // 2 buffers of PT_F
    float* Hst = smem + 2 * PT_F;              // 2 buffers of HS_F (c-major)
    float* zsh = smem + 2 * PT_F + 2 * HS_F;   // 64 floats
    const uint32_t sb = smem_u32(smem);
    const uint32_t HstAddr = sb + (2 * PT_F) * 4;

    const int tid  = threadIdx.x;
    const int wid  = tid >> 5;
    const int lane = tid & 31;
    const int gid  = lane >> 2;
    const int t4   = lane & 3;
    const int i0   = blockIdx.x * 64;
    const int m0   = (wid >> 2) * 16;          // 0/16/32/48
    const int n0   = (wid & 3) * 32;           // 0/32/64/96

    if (tid < 64) zsh[tid] = 0.f;

    // P-build: each thread owns one row, 8 j's
    const int prow = tid >> 3;                 // 0..63
    const int jl0  = (tid & 7) * 8;            // 0..56
    const float2 a12 = g_A12[i0 + prow];
    const float A1 = a12.x, A2 = a12.y;
    const int* arow = adj + (size_t)(i0 + prow) * N_NODES + jl0;

    float acc[4][4];
#pragma unroll
    for (int nb = 0; nb < 4; nb++)
#pragma unroll
        for (int q = 0; q < 4; q++) acc[nb][q] = 0.f;
    float zacc = 0.f;

    // ---- prologue: stage H(0), prefetch adj/E(0) ----
    {
        uint32_t dst = HstAddr;                // buffer 0
#pragma unroll
        for (int q = 0; q < 4; q++) {
            int idx = q * 512 + tid;
            int c = idx >> 4, f4 = idx & 15;
            cp16(dst + (uint32_t)(c * 68 + f4 * 4) * 4,
                 g_hT32 + (size_t)c * N_NODES + f4 * 4);
        }
        cp_commit();
    }
    int4 av0, av1;
    float4 e0, e1, e2, e3;
    {
        av0 = *(const int4*)(arow);
        av1 = *(const int4*)(arow + 4);
        const float4* ep = (const float4*)(g_E12 + jl0);
        e0 = ep[0]; e1 = ep[1]; e2 = ep[2]; e3 = ep[3];
    }

    for (int cc = 0; cc < 128; cc++) {
        const int p = cc & 1;
        float* PtB = Pt + p * PT_F;

        // ---- store P(cc) from prefetched regs ----
        {
            float4 pv0, pv1;
            float q0 = fmaxf(A1 * e0.x, A2 * e0.y);
            float q1 = fmaxf(A1 * e0.z, A2 * e0.w);
            float q2 = fmaxf(A1 * e1.x, A2 * e1.y);
            float q3 = fmaxf(A1 * e1.z, A2 * e1.w);
            pv0.x = (av0.x > 0) ? tf32r(q0) : 0.f;
            pv0.y = (av0.y > 0) ? tf32r(q1) : 0.f;
            pv0.z = (av0.z > 0) ? tf32r(q2) : 0.f;
            pv0.w = (av0.w > 0) ? tf32r(q3) : 0.f;
            q0 = fmaxf(A1 * e2.x, A2 * e2.y);
            q1 = fmaxf(A1 * e2.z, A2 * e2.w);
            q2 = fmaxf(A1 * e3.x, A2 * e3.y);
            q3 = fmaxf(A1 * e3.z, A2 * e3.w);
            pv1.x = (av1.x > 0) ? tf32r(q0) : 0.f;
            pv1.y = (av1.y > 0) ? tf32r(q1) : 0.f;
            pv1.z = (av1.z > 0) ? tf32r(q2) : 0.f;
            pv1.w = (av1.w > 0) ? tf32r(q3) : 0.f;
            zacc += (pv0.x + pv0.y) + (pv0.z + pv0.w)
                  + (pv1.x + pv1.y) + (pv1.z + pv1.w);
            *(float4*)(PtB + prow * 68 + jl0)     = pv0;
            *(float4*)(PtB + prow * 68 + jl0 + 4) = pv1;
        }

        cp_wait0();          // H(cc) resident
        __syncthreads();     // P(cc) visible; MMA(cc-1) complete (buffers reusable)

        // ---- issue async loads for chunk cc+1 (hidden behind MMA phase) ----
        if (cc < 127) {
            const int njb = (cc + 1) << 6;
            uint32_t dst = HstAddr + (uint32_t)(p ^ 1) * HS_F * 4;
            const float* src = g_hT32 + njb;
#pragma unroll
            for (int q = 0; q < 4; q++) {
                int idx = q * 512 + tid;
                int c = idx >> 4, f4 = idx & 15;
                cp16(dst + (uint32_t)(c * 68 + f4 * 4) * 4,
                     src + (size_t)c * N_NODES + f4 * 4);
            }
            cp_commit();
            av0 = *(const int4*)(arow + njb);
            av1 = *(const int4*)(arow + njb + 4);
            const float4* ep = (const float4*)(g_E12 + njb + jl0);
            e0 = ep[0]; e1 = ep[1]; e2 = ep[2]; e3 = ep[3];
        }

        // ---- MMA phase on buffers p ----
        const uint32_t* Pu = (const uint32_t*)(Pt + p * PT_F);
        const uint32_t* Hu = (const uint32_t*)(Hst + p * HS_F);
#pragma unroll
        for (int ks = 0; ks < 8; ks++) {
            const int k0 = ks * 8 + t4;
            uint32_t af[4], bf[4][2];
            int r0 = (m0 + gid) * 68 + k0;
            af[0] = Pu[r0];
            af[1] = Pu[r0 + 8 * 68];
            af[2] = Pu[r0 + 4];
            af[3] = Pu[r0 + 8 * 68 + 4];
#pragma unroll
            for (int nb = 0; nb < 4; nb++) {
                int c0 = (n0 + nb * 8 + gid) * 68 + k0;
                bf[nb][0] = Hu[c0];
                bf[nb][1] = Hu[c0 + 4];
            }
#pragma unroll
            for (int nb = 0; nb < 4; nb++)
                mma8(acc[nb], af, bf[nb]);
        }
        __syncthreads();
    }

    // ---- epilogue: z normalize + write ----
    atomicAdd(&zsh[prow], zacc);
    __syncthreads();
    {
        int r0 = m0 + gid;
        float rz0 = 1.0f / zsh[r0];
        float rz1 = 1.0f / zsh[r0 + 8];
#pragma unroll
        for (int nb = 0; nb < 4; nb++) {
            int col = n0 + nb * 8 + t4 * 2;
            float2 v0 = {acc[nb][0] * rz0, acc[nb][1] * rz0};
            float2 v1 = {acc[nb][2] * rz1, acc[nb][3] * rz1};
            *(float2*)(g_hp + (size_t)(i0 + r0) * OUT_F + col)     = v0;
            *(float2*)(g_hp + (size_t)(i0 + r0 + 8) * OUT_F + col) = v1;
        }
    }
}

// ---------------- K5: BN column stats ----------------
__global__ void k_stats() {
    int col = threadIdx.x & 127;
    int h = threadIdx.x >> 7;
    int r0 = blockIdx.x * 64;
    float s = 0.f, q = 0.f;
    for (int r = h; r < 64; r += 2) {
        float v = g_hp[(size_t)(r0 + r) * OUT_F + col];
        s += v; q = fmaf(v, v, q);
    }
    atomicAdd(&g_colsum[col], s);
    atomicAdd(&g_colsumsq[col], q);
}

// ---------------- K6: BatchNorm + ELU ----------------
__global__ void k_bn(const float* __restrict__ gamma, const float* __restrict__ beta,
                     float* __restrict__ out) {
    int idx = blockIdx.x * blockDim.x + threadIdx.x;
    int col = idx & 127;
    const float invN = 1.0f / (float)N_NODES;
    float mean = g_colsum[col] * invN;
    float var  = g_colsumsq[col] * invN - mean * mean;
    float rstd = rsqrtf(var + BN_EPS);
    float v = (g_hp[idx] - mean) * rstd * gamma[col] + beta[col];
    out[idx] = (v > 0.f) ? v : expm1f(v);
}

// ---------------- launch ----------------
extern "C" void kernel_launch(void* const* d_in, const int* in_sizes, int n_in,
                              void* d_out, int out_size) {
    (void)in_sizes; (void)n_in; (void)out_size;
    const float* inp   = (const float*)d_in[0];
    const int*   adj   = (const int*)  d_in[1];
    const float* W     = (const float*)d_in[2];
    const float* a_vec = (const float*)d_in[3];
    const float* gamma = (const float*)d_in[4];
    const float* beta  = (const float*)d_in[5];
    float* out = (float*)d_out;

    const int ATTN_SMEM = (2 * PT_F + 2 * HS_F + 64) * 4;   // 104704 B
    static int smem_set = 0;
    if (!smem_set) {
        cudaFuncSetAttribute(k_attn, cudaFuncAttributeMaxDynamicSharedMemorySize, ATTN_SMEM);
        smem_set = 1;
    }

    k_ham  <<<256, 256>>>(W);
    k_h    <<<256, 128>>>(inp);
    k_s    <<<1024, 256>>>(a_vec);
    k_prep <<<32, 256>>>();
    k_attn <<<128, 512, ATTN_SMEM>>>(adj);
    k_stats<<<128, 256>>>();
    k_bn   <<<4096, 256>>>(gamma, beta, out);
}

// round 6
// speedup vs baseline: 4.4459x; 1.3045x over previous
#include <cuda_runtime.h>
#include <cuda_fp16.h>
#include <cstdint>

#define N_NODES 8192
#define IN_F    512
#define OUT_F   128
#define ALPHA   0.2f
#define BN_EPS  1e-5f

// ---------------- scratch ----------------
__device__ __align__(16) float  g_ham[IN_F * OUT_F];
__device__ __align__(16) float  g_h[N_NODES * OUT_F];        // fp32 (for k_s)
__device__ __align__(16) __half g_hT16[OUT_F * N_NODES];     // fp16 transposed [c][j]
__device__ __align__(16) float  g_hp[N_NODES * OUT_F];
__device__ float  g_s1[N_NODES];
__device__ float  g_s2[N_NODES];
__device__ unsigned int g_s2max_u;
__device__ __align__(16) float2 g_A12[N_NODES];
__device__ __align__(16) float2 g_E12[N_NODES];
__device__ float g_colsum[OUT_F];
__device__ float g_colsumsq[OUT_F];

// ---------------- helpers ----------------
__device__ __forceinline__ unsigned long long fma2(unsigned long long a,
                                                   unsigned long long b,
                                                   unsigned long long c) {
    unsigned long long d;
    asm("fma.rn.f32x2 %0, %1, %2, %3;" : "=l"(d) : "l"(a), "l"(b), "l"(c));
    return d;
}
__device__ __forceinline__ unsigned long long dup2(float x) {
    unsigned long long d;
    unsigned int u = __float_as_uint(x);
    asm("mov.b64 %0, {%1, %1};" : "=l"(d) : "r"(u));
    return d;
}
__device__ __forceinline__ float2 unpack2(unsigned long long v) {
    float2 f;
    unsigned int lo, hi;
    asm("mov.b64 {%0, %1}, %2;" : "=r"(lo), "=r"(hi) : "l"(v));
    f.x = __uint_as_float(lo);
    f.y = __uint_as_float(hi);
    return f;
}
__device__ __forceinline__ uint32_t smem_u32(const void* p) {
    uint32_t a;
    asm("{ .reg .u64 t; cvta.to.shared.u64 t, %1; cvt.u32.u64 %0, t; }" : "=r"(a) : "l"(p));
    return a;
}
__device__ __forceinline__ void cp16(uint32_t dst, const void* src) {
    asm volatile("cp.async.cg.shared.global [%0], [%1], 16;" :: "r"(dst), "l"(src) : "memory");
}
__device__ __forceinline__ void cp_commit() {
    asm volatile("cp.async.commit_group;" ::: "memory");
}
__device__ __forceinline__ void cp_wait0() {
    asm volatile("cp.async.wait_group 0;" ::: "memory");
}
__device__ __forceinline__ void ldsm4(uint32_t* r, uint32_t addr) {
    asm volatile("ldmatrix.sync.aligned.m8n8.x4.shared.b16 {%0,%1,%2,%3}, [%4];"
                 : "=r"(r[0]), "=r"(r[1]), "=r"(r[2]), "=r"(r[3]) : "r"(addr));
}
// fp16 m16n8k16 mma, fp32 accumulate
__device__ __forceinline__ void mma16(float* c, const uint32_t* a, const uint32_t* b) {
    asm volatile(
        "mma.sync.aligned.m16n8k16.row.col.f32.f16.f16.f32 "
        "{%0,%1,%2,%3}, {%4,%5,%6,%7}, {%8,%9}, {%0,%1,%2,%3};"
        : "+f"(c[0]), "+f"(c[1]), "+f"(c[2]), "+f"(c[3])
        : "r"(a[0]), "r"(a[1]), "r"(a[2]), "r"(a[3]), "r"(b[0]), "r"(b[1]));
}

// ---------------- K1: hamilton + zero accumulators ----------------
__global__ void k_ham(const float* __restrict__ W) {
    int idx = blockIdx.x * blockDim.x + threadIdx.x;
    if (idx < OUT_F) { g_colsum[idx] = 0.f; g_colsumsq[idx] = 0.f; }
    if (idx == 0) g_s2max_u = 0x007FFFFFu;
    int row = idx >> 7;
    int col = idx & 127;
    int rb = row >> 7, rr = row & 127;
    int cb = col >> 5, cc = col & 31;
    const int   comp_t[4][4] = {{0,1,2,3},{1,0,3,2},{2,3,0,1},{3,2,1,0}};
    const float sign_t[4][4] = {{1.f,-1.f,-1.f,-1.f},
                                {1.f, 1.f,-1.f, 1.f},
                                {1.f, 1.f, 1.f,-1.f},
                                {1.f,-1.f, 1.f, 1.f}};
    g_ham[idx] = sign_t[cb][rb] * W[rr * 128 + comp_t[cb][rb] * 32 + cc];
}

// ---------------- K2: h = input @ hamilton (fp32), + transposed fp16 copy ----------------
__global__ void __launch_bounds__(128) k_h(const float* __restrict__ inp) {
    __shared__ __align__(16) float At[32][36];
    __shared__ __align__(16) float Bs[32][132];
    int tid = threadIdx.x;
    int tx = tid & 15, ty = tid >> 4;
    int i0 = blockIdx.x * 32;
    unsigned long long acc[4][4];
#pragma unroll
    for (int r = 0; r < 4; r++)
#pragma unroll
        for (int cp = 0; cp < 4; cp++) acc[r][cp] = 0ull;

    for (int kb = 0; kb < IN_F; kb += 32) {
#pragma unroll
        for (int q = 0; q < 2; q++) {
            int idx = tid * 2 + q;
            int row = idx >> 3, c4 = idx & 7;
            float4 v = *(const float4*)(inp + (size_t)(i0 + row) * IN_F + kb + c4 * 4);
            At[c4 * 4 + 0][row] = v.x;
            At[c4 * 4 + 1][row] = v.y;
            At[c4 * 4 + 2][row] = v.z;
            At[c4 * 4 + 3][row] = v.w;
        }
#pragma unroll
        for (int q = 0; q < 8; q++) {
            int idx = q * 128 + tid;
            int row = idx >> 5, c4 = idx & 31;
            *(float4*)&Bs[row][c4 * 4] = *(const float4*)(g_ham + (kb + row) * OUT_F + c4 * 4);
        }
        __syncthreads();
#pragma unroll
        for (int kk = 0; kk < 32; kk++) {
            float4 a = *(float4*)&At[kk][ty * 4];
            ulonglong2 b01 = *(ulonglong2*)&Bs[kk][tx * 8];
            ulonglong2 b23 = *(ulonglong2*)&Bs[kk][tx * 8 + 4];
            unsigned long long bb[4] = {b01.x, b01.y, b23.x, b23.y};
            float av[4] = {a.x, a.y, a.z, a.w};
#pragma unroll
            for (int r = 0; r < 4; r++) {
                unsigned long long pd = dup2(av[r]);
#pragma unroll
                for (int cp = 0; cp < 4; cp++) acc[r][cp] = fma2(pd, bb[cp], acc[r][cp]);
            }
        }
        __syncthreads();
    }
    float o[4][8];
#pragma unroll
    for (int r = 0; r < 4; r++)
#pragma unroll
        for (int cp = 0; cp < 4; cp++) {
            float2 v = unpack2(acc[r][cp]);
            o[r][2 * cp] = v.x; o[r][2 * cp + 1] = v.y;
        }
#pragma unroll
    for (int r = 0; r < 4; r++) {
        int gi = i0 + ty * 4 + r;
        float4 o0 = {o[r][0], o[r][1], o[r][2], o[r][3]};
        float4 o1 = {o[r][4], o[r][5], o[r][6], o[r][7]};
        *(float4*)(g_h + (size_t)gi * OUT_F + tx * 8)     = o0;
        *(float4*)(g_h + (size_t)gi * OUT_F + tx * 8 + 4) = o1;
    }
#pragma unroll
    for (int c = 0; c < 8; c++) {
        __half2 lo = __floats2half2_rn(o[0][c], o[1][c]);
        __half2 hi = __floats2half2_rn(o[2][c], o[3][c]);
        uint2 st = { *(uint32_t*)&lo, *(uint32_t*)&hi };
        *(uint2*)(g_hT16 + (size_t)(tx * 8 + c) * N_NODES + i0 + ty * 4) = st;
    }
}

// ---------------- K3: s1/s2 per row + global s2 max ----------------
__global__ void k_s(const float* __restrict__ a_vec) {
    __shared__ float s2b[8];
    int tid = threadIdx.x;
    int warp = (blockIdx.x * blockDim.x + tid) >> 5;
    int lane = tid & 31;
    float s1 = 0.f, s2 = 0.f;
#pragma unroll
    for (int q = 0; q < 4; q++) {
        int c = lane + q * 32;
        float hv = g_h[(size_t)warp * OUT_F + c];
        s1 = fmaf(hv, a_vec[c], s1);
        s2 = fmaf(hv, a_vec[OUT_F + c], s2);
    }
#pragma unroll
    for (int off = 16; off > 0; off >>= 1) {
        s1 += __shfl_xor_sync(0xffffffffu, s1, off);
        s2 += __shfl_xor_sync(0xffffffffu, s2, off);
    }
    if (lane == 0) {
        g_s1[warp] = s1; g_s2[warp] = s2;
        s2b[tid >> 5] = s2;
    }
    __syncthreads();
    if (tid == 0) {
        float m = s2b[0];
#pragma unroll
        for (int w = 1; w < 8; w++) m = fmaxf(m, s2b[w]);
        uint32_t u = __float_as_uint(m);
        u = (u & 0x80000000u) ? ~u : (u | 0x80000000u);
        atomicMax(&g_s2max_u, u);
    }
}

// ---------------- K3b: per-node exp factors ----------------
__global__ void k_prep() {
    int i = blockIdx.x * blockDim.x + threadIdx.x;
    uint32_t mu = g_s2max_u;
    float s2max = (mu & 0x80000000u) ? __uint_as_float(mu ^ 0x80000000u)
                                     : __uint_as_float(~mu);
    float s1 = g_s1[i], s2 = g_s2[i];
    float m = s1 + s2max;
    m = (m > 0.f) ? m : ALPHA * m;
    g_A12[i] = make_float2(__expf(s1 - m), __expf(ALPHA * s1 - m));
    g_E12[i] = make_float2(__expf(s2), __expf(ALPHA * s2));
}

// ---------------- K4: fused attention via fp16 mma.sync, pipelined ----------------
// 128 CTAs x 256 thr (8 warps 2x4, warp tile 32x32). BM=64, BN=128, BK=64.
#define PT_B 9216            // 64 rows * 144 B (72 halves)
#define HS_B 18432           // 128 rows * 144 B
#define E_OFF  (2*PT_B + 2*HS_B)       // 55296
#define Z_OFF  (E_OFF + 1024)          // 56320
#define ATTN_SMEM (Z_OFF + 256)        // 56576
__global__ void __launch_bounds__(256, 2) k_attn(const int* __restrict__ adj) {
    extern __shared__ __align__(16) char smem[];
    const uint32_t sb = smem_u32(smem);
    float* zsh = (float*)(smem + Z_OFF);

    const int tid  = threadIdx.x;
    const int wid  = tid >> 5;
    const int lane = tid & 31;
    const int gid  = lane >> 2;
    const int t4   = lane & 3;
    const int i0   = blockIdx.x * 64;
    const int m0   = (wid >> 2) * 32;          // 0/32
    const int n0   = (wid & 3) * 32;           // 0/32/64/96

    if (tid < 64) zsh[tid] = 0.f;

    // P-build: thread owns row = tid>>2, 16 j's at j0
    const int prow = tid >> 2;                 // 0..63
    const int jl0  = (tid & 3) * 16;           // 0/16/32/48
    const float2 a12 = g_A12[i0 + prow];
    const float A1 = a12.x, A2 = a12.y;
    const int* arow = adj + (size_t)(i0 + prow) * N_NODES + jl0;

    // ldmatrix lane-address offsets (relative to buffer base)
    const uint32_t aoffr = (uint32_t)((m0 + (lane & 7) + ((lane >> 3) & 1) * 8) * 144
                                      + ((lane >> 4) & 1) * 16);
    const uint32_t boffr = (uint32_t)((n0 + (lane & 7) + ((lane >> 4) & 1) * 8) * 144
                                      + ((lane >> 3) & 1) * 16);

    float acc[2][4][4];
#pragma unroll
    for (int mb = 0; mb < 2; mb++)
#pragma unroll
        for (int nb = 0; nb < 4; nb++)
#pragma unroll
            for (int q = 0; q < 4; q++) acc[mb][nb][q] = 0.f;
    float zacc = 0.f;

    // ---- prologue: stage H(0), E(0); prefetch adj(0) ----
    {
        uint32_t hdst = sb + 2 * PT_B;
#pragma unroll
        for (int q = 0; q < 4; q++) {
            int idx = q * 256 + tid;
            int c = idx >> 3, f8 = idx & 7;
            cp16(hdst + (uint32_t)(c * 144 + f8 * 16),
                 g_hT16 + (size_t)c * N_NODES + f8 * 8);
        }
        if (tid < 32) cp16(sb + E_OFF + tid * 16, g_E12 + tid * 2);
        cp_commit();
    }
    int4 av[4];
#pragma unroll
    for (int g = 0; g < 4; g++) av[g] = *(const int4*)(arow + g * 4);

    for (int cc = 0; cc < 128; cc++) {
        const int p = cc & 1;

        cp_wait0();
        __syncthreads();     // H(cc),E(cc) visible; MMA(cc-1) done

        // ---- build P(cc) ----
        {
            char* PtB = smem + p * PT_B;
            const float2* E = (const float2*)(smem + E_OFF + p * 512);
#pragma unroll
            for (int g = 0; g < 4; g++) {
                int jj = jl0 + g * 4;
                int4 a = av[g];
                float2 e0 = E[jj], e1 = E[jj + 1], e2 = E[jj + 2], e3 = E[jj + 3];
                float q0 = fmaxf(A1 * e0.x, A2 * e0.y);
                float q1 = fmaxf(A1 * e1.x, A2 * e1.y);
                float q2 = fmaxf(A1 * e2.x, A2 * e2.y);
                float q3 = fmaxf(A1 * e3.x, A2 * e3.y);
                if (a.x <= 0) q0 = 0.f;
                if (a.y <= 0) q1 = 0.f;
                if (a.z <= 0) q2 = 0.f;
                if (a.w <= 0) q3 = 0.f;
                __half2 h20 = __floats2half2_rn(q0, q1);
                __half2 h21 = __floats2half2_rn(q2, q3);
                float2 f0 = __half22float2(h20);
                float2 f1 = __half22float2(h21);
                zacc += (f0.x + f0.y) + (f1.x + f1.y);
                uint2 st = { *(uint32_t*)&h20, *(uint32_t*)&h21 };
                *(uint2*)(PtB + prow * 144 + jj * 2) = st;
            }
        }

        // ---- issue async loads for chunk cc+1 ----
        if (cc < 127) {
            const int njb = (cc + 1) << 6;
            uint32_t hdst = sb + 2 * PT_B + (uint32_t)(p ^ 1) * HS_B;
            const __half* src = g_hT16 + njb;
#pragma unroll
            for (int q = 0; q < 4; q++) {
                int idx = q * 256 + tid;
                int c = idx >> 3, f8 = idx & 7;
                cp16(hdst + (uint32_t)(c * 144 + f8 * 16),
                     src + (size_t)c * N_NODES + f8 * 8);
            }
            if (tid < 32) cp16(sb + E_OFF + (uint32_t)(p ^ 1) * 512 + tid * 16,
                               g_E12 + njb + tid * 2);
            cp_commit();
#pragma unroll
            for (int g = 0; g < 4; g++) av[g] = *(const int4*)(arow + njb + g * 4);
        }

        __syncthreads();     // P(cc) visible to all warps

        // ---- MMA phase on buffers p ----
        {
            const uint32_t pa = sb + (uint32_t)p * PT_B + aoffr;
            const uint32_t pb = sb + 2 * PT_B + (uint32_t)p * HS_B + boffr;
#pragma unroll
            for (int ks = 0; ks < 4; ks++) {
                uint32_t a0[4], a1[4], b01[4], b23[4];
                ldsm4(a0, pa + ks * 32);
                ldsm4(a1, pa + ks * 32 + 16 * 144);
                ldsm4(b01, pb + ks * 32);
                ldsm4(b23, pb + ks * 32 + 16 * 144);
                mma16(acc[0][0], a0, b01 + 0);
                mma16(acc[0][1], a0, b01 + 2);
                mma16(acc[0][2], a0, b23 + 0);
                mma16(acc[0][3], a0, b23 + 2);
                mma16(acc[1][0], a1, b01 + 0);
                mma16(acc[1][1], a1, b01 + 2);
                mma16(acc[1][2], a1, b23 + 0);
                mma16(acc[1][3], a1, b23 + 2);
            }
        }
    }

    // ---- epilogue: z normalize + write ----
    atomicAdd(&zsh[prow], zacc);
    __syncthreads();
#pragma unroll
    for (int mb = 0; mb < 2; mb++) {
        int r0 = m0 + mb * 16 + gid;
        float rz0 = 1.0f / zsh[r0];
        float rz1 = 1.0f / zsh[r0 + 8];
#pragma unroll
        for (int nb = 0; nb < 4; nb++) {
            int col = n0 + nb * 8 + t4 * 2;
            float2 v0 = {acc[mb][nb][0] * rz0, acc[mb][nb][1] * rz0};
            float2 v1 = {acc[mb][nb][2] * rz1, acc[mb][nb][3] * rz1};
            *(float2*)(g_hp + (size_t)(i0 + r0) * OUT_F + col)     = v0;
            *(float2*)(g_hp + (size_t)(i0 + r0 + 8) * OUT_F + col) = v1;
        }
    }
}

// ---------------- K5: BN column stats ----------------
__global__ void k_stats() {
    int col = threadIdx.x & 127;
    int h = threadIdx.x >> 7;
    int r0 = blockIdx.x * 64;
    float s = 0.f, q = 0.f;
    for (int r = h; r < 64; r += 2) {
        float v = g_hp[(size_t)(r0 + r) * OUT_F + col];
        s += v; q = fmaf(v, v, q);
    }
    atomicAdd(&g_colsum[col], s);
    atomicAdd(&g_colsumsq[col], q);
}

// ---------------- K6: BatchNorm + ELU ----------------
__global__ void k_bn(const float* __restrict__ gamma, const float* __restrict__ beta,
                     float* __restrict__ out) {
    int idx = blockIdx.x * blockDim.x + threadIdx.x;
    int col = idx & 127;
    const float invN = 1.0f / (float)N_NODES;
    float mean = g_colsum[col] * invN;
    float var  = g_colsumsq[col] * invN - mean * mean;
    float rstd = rsqrtf(var + BN_EPS);
    float v = (g_hp[idx] - mean) * rstd * gamma[col] + beta[col];
    out[idx] = (v > 0.f) ? v : expm1f(v);
}

// ---------------- launch ----------------
extern "C" void kernel_launch(void* const* d_in, const int* in_sizes, int n_in,
                              void* d_out, int out_size) {
    (void)in_sizes; (void)n_in; (void)out_size;
    const float* inp   = (const float*)d_in[0];
    const int*   adj   = (const int*)  d_in[1];
    const float* W     = (const float*)d_in[2];
    const float* a_vec = (const float*)d_in[3];
    const float* gamma = (const float*)d_in[4];
    const float* beta  = (const float*)d_in[5];
    float* out = (float*)d_out;

    static int smem_set = 0;
    if (!smem_set) {
        cudaFuncSetAttribute(k_attn, cudaFuncAttributeMaxDynamicSharedMemorySize, ATTN_SMEM);
        smem_set = 1;
    }

    k_ham  <<<256, 256>>>(W);
    k_h    <<<256, 128>>>(inp);
    k_s    <<<1024, 256>>>(a_vec);
    k_prep <<<32, 256>>>();
    k_attn <<<128, 256, ATTN_SMEM>>>(adj);
    k_stats<<<128, 256>>>();
    k_bn   <<<4096, 256>>>(gamma, beta, out);
}

// round 8
// speedup vs baseline: 6.2831x; 1.4132x over previous
#include <cuda_runtime.h>
#include <cuda_fp16.h>
#include <cstdint>

#define N_NODES 8192
#define IN_F    512
#define OUT_F   128
#define ALPHA   0.2f
#define BN_EPS  1e-5f

// ---------------- scratch ----------------
__device__ __align__(16) float  g_h[N_NODES * OUT_F];        // fp32 (for k_s)
__device__ __align__(16) __half g_hT16[OUT_F * N_NODES];     // fp16 transposed [c][j]
__device__ __align__(16) float  g_hp[N_NODES * OUT_F];       // merged h'
__device__ __align__(16) float  g_hp0[N_NODES * OUT_F];      // partial, j-half 0
__device__ __align__(16) float  g_hp1[N_NODES * OUT_F];      // partial, j-half 1
__device__ float  g_z0[N_NODES];
__device__ float  g_z1[N_NODES];
__device__ float  g_s1[N_NODES];
__device__ float  g_s2[N_NODES];
__device__ unsigned int g_s2max_u = 0x007FFFFFu;             // encoded -inf (idempotent)
__device__ __align__(16) float2   g_A12[N_NODES];            // fp32 {A1, A2}
__device__ __align__(8)  uint32_t g_E12h[N_NODES];           // half2 {E1, E2}, both <= 1
__device__ float g_colsum[OUT_F];
__device__ float g_colsumsq[OUT_F];

// ---------------- helpers ----------------
__device__ __forceinline__ unsigned long long fma2(unsigned long long a,
                                                   unsigned long long b,
                                                   unsigned long long c) {
    unsigned long long d;
    asm("fma.rn.f32x2 %0, %1, %2, %3;" : "=l"(d) : "l"(a), "l"(b), "l"(c));
    return d;
}
__device__ __forceinline__ unsigned long long dup2(float x) {
    unsigned long long d;
    unsigned int u = __float_as_uint(x);
    asm("mov.b64 %0, {%1, %1};" : "=l"(d) : "r"(u));
    return d;
}
__device__ __forceinline__ float2 unpack2(unsigned long long v) {
    float2 f;
    unsigned int lo, hi;
    asm("mov.b64 {%0, %1}, %2;" : "=r"(lo), "=r"(hi) : "l"(v));
    f.x = __uint_as_float(lo);
    f.y = __uint_as_float(hi);
    return f;
}
__device__ __forceinline__ uint32_t smem_u32(const void* p) {
    uint32_t a;
    asm("{ .reg .u64 t; cvta.to.shared.u64 t, %1; cvt.u32.u64 %0, t; }" : "=r"(a) : "l"(p));
    return a;
}
__device__ __forceinline__ void cp16(uint32_t dst, const void* src) {
    asm volatile("cp.async.cg.shared.global [%0], [%1], 16;" :: "r"(dst), "l"(src) : "memory");
}
__device__ __forceinline__ void cp_commit() {
    asm volatile("cp.async.commit_group;" ::: "memory");
}
__device__ __forceinline__ void cp_wait0() {
    asm volatile("cp.async.wait_group 0;" ::: "memory");
}
__device__ __forceinline__ void cp_wait1() {
    asm volatile("cp.async.wait_group 1;" ::: "memory");
}
__device__ __forceinline__ void ldsm4(uint32_t* r, uint32_t addr) {
    asm volatile("ldmatrix.sync.aligned.m8n8.x4.shared.b16 {%0,%1,%2,%3}, [%4];"
                 : "=r"(r[0]), "=r"(r[1]), "=r"(r[2]), "=r"(r[3]) : "r"(addr));
}
__device__ __forceinline__ void mma16(float* c, const uint32_t* a, const uint32_t* b) {
    asm volatile(
        "mma.sync.aligned.m16n8k16.row.col.f32.f16.f16.f32 "
        "{%0,%1,%2,%3}, {%4,%5,%6,%7}, {%8,%9}, {%0,%1,%2,%3};"
        : "+f"(c[0]), "+f"(c[1]), "+f"(c[2]), "+f"(c[3])
        : "r"(a[0]), "r"(a[1]), "r"(a[2]), "r"(a[3]), "r"(b[0]), "r"(b[1]));
}

// ---------------- K1: h = input @ hamilton (built inline), + fp16 transposed copy ----------------
__global__ void __launch_bounds__(128) k_h(const float* __restrict__ inp,
                                           const float* __restrict__ W) {
    __shared__ __align__(16) float At[32][36];
    __shared__ __align__(16) float Bs[32][132];
    int tid = threadIdx.x;
    int tx = tid & 15, ty = tid >> 4;
    int i0 = blockIdx.x * 32;
    unsigned long long acc[4][4];
#pragma unroll
    for (int r = 0; r < 4; r++)
#pragma unroll
        for (int cp = 0; cp < 4; cp++) acc[r][cp] = 0ull;

    for (int kb = 0; kb < IN_F; kb += 32) {
#pragma unroll
        for (int q = 0; q < 2; q++) {
            int idx = tid * 2 + q;
            int row = idx >> 3, c4 = idx & 7;
            float4 v = *(const float4*)(inp + (size_t)(i0 + row) * IN_F + kb + c4 * 4);
            At[c4 * 4 + 0][row] = v.x;
            At[c4 * 4 + 1][row] = v.y;
            At[c4 * 4 + 2][row] = v.z;
            At[c4 * 4 + 3][row] = v.w;
        }
        // hamilton built on the fly: ham[hr][col] = sign(rb,cb) * W[rr][(rb^cb)*32 + cc]
#pragma unroll
        for (int q = 0; q < 8; q++) {
            int idx = q * 128 + tid;
            int row = idx >> 5, c4 = idx & 31;
            int hr = kb + row;
            int rb = hr >> 7, rr = hr & 127;
            int cb = c4 >> 3;
            int cc4 = (c4 & 7) * 4;
            int comp = rb ^ cb;
            float sgn = 1.f;
            if (cb == 0) { if (rb != 0) sgn = -1.f; }
            else if (rb == (cb % 3) + 1) sgn = -1.f;
            float4 v = *(const float4*)(W + rr * 128 + comp * 32 + cc4);
            v.x *= sgn; v.y *= sgn; v.z *= sgn; v.w *= sgn;
            *(float4*)&Bs[row][c4 * 4] = v;
        }
        __syncthreads();
#pragma unroll
        for (int kk = 0; kk < 32; kk++) {
            float4 a = *(float4*)&At[kk][ty * 4];
            ulonglong2 b01 = *(ulonglong2*)&Bs[kk][tx * 8];
            ulonglong2 b23 = *(ulonglong2*)&Bs[kk][tx * 8 + 4];
            unsigned long long bb[4] = {b01.x, b01.y, b23.x, b23.y};
            float av[4] = {a.x, a.y, a.z, a.w};
#pragma unroll
            for (int r = 0; r < 4; r++) {
                unsigned long long pd = dup2(av[r]);
#pragma unroll
                for (int cp = 0; cp < 4; cp++) acc[r][cp] = fma2(pd, bb[cp], acc[r][cp]);
            }
        }
        __syncthreads();
    }
    float o[4][8];
#pragma unroll
    for (int r = 0; r < 4; r++)
#pragma unroll
        for (int cp = 0; cp < 4; cp++) {
            float2 v = unpack2(acc[r][cp]);
            o[r][2 * cp] = v.x; o[r][2 * cp + 1] = v.y;
        }
#pragma unroll
    for (int r = 0; r < 4; r++) {
        int gi = i0 + ty * 4 + r;
        float4 o0 = {o[r][0], o[r][1], o[r][2], o[r][3]};
        float4 o1 = {o[r][4], o[r][5], o[r][6], o[r][7]};
        *(float4*)(g_h + (size_t)gi * OUT_F + tx * 8)     = o0;
        *(float4*)(g_h + (size_t)gi * OUT_F + tx * 8 + 4) = o1;
    }
#pragma unroll
    for (int c = 0; c < 8; c++) {
        __half2 lo = __floats2half2_rn(o[0][c], o[1][c]);
        __half2 hi = __floats2half2_rn(o[2][c], o[3][c]);
        uint2 st = { *(uint32_t*)&lo, *(uint32_t*)&hi };
        *(uint2*)(g_hT16 + (size_t)(tx * 8 + c) * N_NODES + i0 + ty * 4) = st;
    }
}

// ---------------- K2: s1/s2 per row + global s2 max ----------------
__global__ void k_s(const float* __restrict__ a_vec) {
    __shared__ float s2b[8];
    int tid = threadIdx.x;
    int warp = (blockIdx.x * blockDim.x + tid) >> 5;
    int lane = tid & 31;
    float s1 = 0.f, s2 = 0.f;
#pragma unroll
    for (int q = 0; q < 4; q++) {
        int c = lane + q * 32;
        float hv = g_h[(size_t)warp * OUT_F + c];
        s1 = fmaf(hv, a_vec[c], s1);
        s2 = fmaf(hv, a_vec[OUT_F + c], s2);
    }
#pragma unroll
    for (int off = 16; off > 0; off >>= 1) {
        s1 += __shfl_xor_sync(0xffffffffu, s1, off);
        s2 += __shfl_xor_sync(0xffffffffu, s2, off);
    }
    if (lane == 0) {
        g_s1[warp] = s1; g_s2[warp] = s2;
        s2b[tid >> 5] = s2;
    }
    __syncthreads();
    if (tid == 0) {
        float m = s2b[0];
#pragma unroll
        for (int w = 1; w < 8; w++) m = fmaxf(m, s2b[w]);
        uint32_t u = __float_as_uint(m);
        u = (u & 0x80000000u) ? ~u : (u | 0x80000000u);
        atomicMax(&g_s2max_u, u);
    }
}

// ---------------- K3: per-node exp factors (rescaled so all <= 1), + zero BN sums ----------------
__global__ void k_prep() {
    int i = blockIdx.x * blockDim.x + threadIdx.x;
    if (blockIdx.x == 0 && threadIdx.x < 128) {
        g_colsum[threadIdx.x] = 0.f; g_colsumsq[threadIdx.x] = 0.f;
    }
    uint32_t mu = g_s2max_u;
    float s2max = (mu & 0x80000000u) ? __uint_as_float(mu ^ 0x80000000u)
                                     : __uint_as_float(~mu);
    float s1 = g_s1[i], s2 = g_s2[i];
    float t = s1 + s2max;
    float m = (t > 0.f) ? t : ALPHA * t;
    // A1*E1 = exp(s1+s2-m); A2*E2 = exp(0.2(s1+s2)-m); all four factors in (0,1]
    float A1 = __expf(s1 + s2max - m);
    float A2 = __expf(ALPHA * (s1 + s2max) - m);
    float E1 = __expf(s2 - s2max);
    float E2 = __expf(ALPHA * (s2 - s2max));
    g_A12[i] = make_float2(A1, A2);
    __half2 e = __floats2half2_rn(E1, E2);
    g_E12h[i] = *(uint32_t*)&e;
}

// ---------------- K4: fused attention, fp16 mma.sync, 3-stage pipeline, split-j ----------------
// 256 CTAs x 256 thr (8 warps 2x4, warp tile 32x32). BM=64, BN=128, BK=64, 64 chunks.
#define PT_B 9216                         // 64 rows * 144 B
#define HS_B 18432                        // 128 rows * 144 B
#define H_OFF (2 * PT_B)                  // 18432
#define Z_OFF (H_OFF + 3 * HS_B)          // 73728
#define ATTN_SMEM (Z_OFF + 256)           // 73984
__global__ void __launch_bounds__(256, 2) k_attn(const int* __restrict__ adj) {
    extern __shared__ __align__(16) char smem[];
    const uint32_t sb = smem_u32(smem);
    float* zsh = (float*)(smem + Z_OFF);

    const int tid  = threadIdx.x;
    const int wid  = tid >> 5;
    const int lane = tid & 31;
    const int gid  = lane >> 2;
    const int t4   = lane & 3;
    const int bid  = blockIdx.x;
    const int i0   = (bid >> 1) * 64;
    const int jb0  = (bid & 1) * 4096;     // j-half base
    const int m0   = (wid >> 2) * 32;
    const int n0   = (wid & 3) * 32;

    if (tid < 64) zsh[tid] = 0.f;

    const int prow = tid >> 2;             // 0..63
    const int jl0  = (tid & 3) * 16;       // 0/16/32/48
    const float2 a12 = g_A12[i0 + prow];
    const float A1 = a12.x, A2 = a12.y;
    const int* arow = adj + (size_t)(i0 + prow) * N_NODES + jb0 + jl0;
    const uint32_t* esrc = g_E12h + jb0 + jl0;

    const uint32_t aoffr = (uint32_t)((m0 + (lane & 7) + ((lane >> 3) & 1) * 8) * 144
                                      + ((lane >> 4) & 1) * 16);
    const uint32_t boffr = (uint32_t)((n0 + (lane & 7) + ((lane >> 4) & 1) * 8) * 144
                                      + ((lane >> 3) & 1) * 16);

    float acc[2][4][4];
#pragma unroll
    for (int mb = 0; mb < 2; mb++)
#pragma unroll
        for (int nb = 0; nb < 4; nb++)
#pragma unroll
            for (int q = 0; q < 4; q++) acc[mb][nb][q] = 0.f;
    float zacc = 0.f;

    // ---- prologue: stage H(0), H(1); prefetch adj/E(0) into regs ----
#pragma unroll
    for (int s = 0; s < 2; s++) {
        uint32_t hdst = sb + H_OFF + (uint32_t)s * HS_B;
        const __half* src = g_hT16 + jb0 + s * 64;
#pragma unroll
        for (int q = 0; q < 4; q++) {
            int idx = q * 256 + tid;
            int c = idx >> 3, f8 = idx & 7;
            cp16(hdst + (uint32_t)(c * 144 + f8 * 16),
                 src + (size_t)c * N_NODES + f8 * 8);
        }
        cp_commit();
    }
    int4 av[4];
    uint4 ew[4];
#pragma unroll
    for (int g = 0; g < 4; g++) av[g] = *(const int4*)(arow + g * 4);
#pragma unroll
    for (int g = 0; g < 4; g++) ew[g] = *(const uint4*)(esrc + g * 4);

    for (int cc = 0; cc < 64; cc++) {
        const int p = cc & 1;
        const int hb = cc - (cc / 3) * 3;      // cc % 3

        // ---- build P(cc) from registers (16 j's per thread) ----
        {
            char* PtB = smem + p * PT_B;
#pragma unroll
            for (int g = 0; g < 4; g++) {
                int4 a = av[g];
                float2 f0 = __half22float2(*(__half2*)&ew[g].x);
                float2 f1 = __half22float2(*(__half2*)&ew[g].y);
                float2 f2 = __half22float2(*(__half2*)&ew[g].z);
                float2 f3 = __half22float2(*(__half2*)&ew[g].w);
                float q0 = fmaxf(A1 * f0.x, A2 * f0.y);
                float q1 = fmaxf(A1 * f1.x, A2 * f1.y);
                float q2 = fmaxf(A1 * f2.x, A2 * f2.y);
                float q3 = fmaxf(A1 * f3.x, A2 * f3.y);
                if (a.x <= 0) q0 = 0.f;
                if (a.y <= 0) q1 = 0.f;
                if (a.z <= 0) q2 = 0.f;
                if (a.w <= 0) q3 = 0.f;
                __half2 h20 = __floats2half2_rn(q0, q1);
                __half2 h21 = __floats2half2_rn(q2, q3);
                float2 r0 = __half22float2(h20);
                float2 r1 = __half22float2(h21);
                zacc += (r0.x + r0.y) + (r1.x + r1.y);
                uint2 st = { *(uint32_t*)&h20, *(uint32_t*)&h21 };
                *(uint2*)(PtB + prow * 144 + (jl0 + g * 4) * 2) = st;
            }
        }

        // ---- prefetch adj/E for cc+1 (in flight across MMA) ----
        if (cc < 63) {
            const int nj = (cc + 1) * 64;
#pragma unroll
            for (int g = 0; g < 4; g++) av[g] = *(const int4*)(arow + nj + g * 4);
#pragma unroll
            for (int g = 0; g < 4; g++) ew[g] = *(const uint4*)(esrc + nj + g * 4);
        }

        if (cc < 62) cp_wait1(); else cp_wait0();
        __syncthreads();     // P(cc) visible; H(cc) resident; MMA(cc-1) complete

        // ---- stage H(cc+2) ----
        if (cc + 2 < 64) {
            const int hb2 = (cc + 2) - ((cc + 2) / 3) * 3;
            uint32_t hdst = sb + H_OFF + (uint32_t)hb2 * HS_B;
            const __half* src = g_hT16 + jb0 + (cc + 2) * 64;
#pragma unroll
            for (int q = 0; q < 4; q++) {
                int idx = q * 256 + tid;
                int c = idx >> 3, f8 = idx & 7;
                cp16(hdst + (uint32_t)(c * 144 + f8 * 16),
                     src + (size_t)c * N_NODES + f8 * 8);
            }
            cp_commit();
        }

        // ---- MMA(cc): A from Pbuf[p], B from Hbuf[hb] ----
        {
            const uint32_t pa = sb + (uint32_t)p * PT_B + aoffr;
            const uint32_t pb = sb + H_OFF + (uint32_t)hb * HS_B + boffr;
#pragma unroll
            for (int ks = 0; ks < 4; ks++) {
                uint32_t a0[4], a1[4], b01[4], b23[4];
                ldsm4(a0, pa + ks * 32);
                ldsm4(a1, pa + ks * 32 + 16 * 144);
                ldsm4(b01, pb + ks * 32);
                ldsm4(b23, pb + ks * 32 + 16 * 144);
                mma16(acc[0][0], a0, b01 + 0);
                mma16(acc[0][1], a0, b01 + 2);
                mma16(acc[0][2], a0, b23 + 0);
                mma16(acc[0][3], a0, b23 + 2);
                mma16(acc[1][0], a1, b01 + 0);
                mma16(acc[1][1], a1, b01 + 2);
                mma16(acc[1][2], a1, b23 + 0);
                mma16(acc[1][3], a1, b23 + 2);
            }
        }
    }

    // ---- epilogue: write UNnormalized partials + z ----
    atomicAdd(&zsh[prow], zacc);
    __syncthreads();
    float* hpD = (bid & 1) ? g_hp1 : g_hp0;
    float* zD  = (bid & 1) ? g_z1  : g_z0;
    if (tid < 64) zD[i0 + tid] = zsh[tid];
#pragma unroll
    for (int mb = 0; mb < 2; mb++) {
        int r0 = m0 + mb * 16 + gid;
#pragma unroll
        for (int nb = 0; nb < 4; nb++) {
            int col = n0 + nb * 8 + t4 * 2;
            float2 v0 = {acc[mb][nb][0], acc[mb][nb][1]};
            float2 v1 = {acc[mb][nb][2], acc[mb][nb][3]};
            *(float2*)(hpD + (size_t)(i0 + r0) * OUT_F + col)     = v0;
            *(float2*)(hpD + (size_t)(i0 + r0 + 8) * OUT_F + col) = v1;
        }
    }
}

// ---------------- K5: merge halves, normalize, BN column stats ----------------
__global__ void k_stats() {
    int col = threadIdx.x & 127;
    int h = threadIdx.x >> 7;
    int r0 = blockIdx.x * 64;
    float s = 0.f, q = 0.f;
    for (int r = h; r < 64; r += 2) {
        int row = r0 + r;
        size_t idx = (size_t)row * OUT_F + col;
        float z = g_z0[row] + g_z1[row];
        float m = (g_hp0[idx] + g_hp1[idx]) / z;
        g_hp[idx] = m;
        s += m; q = fmaf(m, m, q);
    }
    atomicAdd(&g_colsum[col], s);
    atomicAdd(&g_colsumsq[col], q);
}

// ---------------- K6: BatchNorm + ELU ----------------
__global__ void k_bn(const float* __restrict__ gamma, const float* __restrict__ beta,
                     float* __restrict__ out) {
    int idx = blockIdx.x * blockDim.x + threadIdx.x;
    int col = idx & 127;
    const float invN = 1.0f / (float)N_NODES;
    float mean = g_colsum[col] * invN;
    float var  = g_colsumsq[col] * invN - mean * mean;
    float rstd = rsqrtf(var + BN_EPS);
    float v = (g_hp[idx] - mean) * rstd * gamma[col] + beta[col];
    out[idx] = (v > 0.f) ? v : expm1f(v);
}

// ---------------- launch ----------------
extern "C" void kernel_launch(void* const* d_in, const int* in_sizes, int n_in,
                              void* d_out, int out_size) {
    (void)in_sizes; (void)n_in; (void)out_size;
    const float* inp   = (const float*)d_in[0];
    const int*   adj   = (const int*)  d_in[1];
    const float* W     = (const float*)d_in[2];
    const float* a_vec = (const float*)d_in[3];
    const float* gamma = (const float*)d_in[4];
    const float* beta  = (const float*)d_in[5];
    float* out = (float*)d_out;

    static int smem_set = 0;
    if (!smem_set) {
        cudaFuncSetAttribute(k_attn, cudaFuncAttributeMaxDynamicSharedMemorySize, ATTN_SMEM);
        smem_set = 1;
    }

    k_h    <<<256, 128>>>(inp, W);
    k_s    <<<1024, 256>>>(a_vec);
    k_prep <<<32, 256>>>();
    k_attn <<<256, 256, ATTN_SMEM>>>(adj);     // launch #4 -> ncu captures this
    k_stats<<<128, 256>>>();
    k_bn   <<<4096, 256>>>(gamma, beta, out);
}

// round 9
// speedup vs baseline: 7.9867x; 1.2711x over previous
#include <cuda_runtime.h>
#include <cuda_fp16.h>
#include <cstdint>

#define N_NODES 8192
#define IN_F    512
#define OUT_F   128
#define ALPHA   0.2f
#define BN_EPS  1e-5f

// ---------------- scratch ----------------
__device__ __align__(16) __half g_ham16T[OUT_F * IN_F];      // [c][k] fp16, 128x512
__device__ __align__(16) float  g_h[N_NODES * OUT_F];        // fp32 (unused downstream except via stage)
__device__ __align__(16) __half g_hT16[OUT_F * N_NODES];     // fp16 transposed [c][j]
__device__ __align__(16) float  g_hp[N_NODES * OUT_F];       // merged h'
__device__ __align__(16) float  g_hp0[N_NODES * OUT_F];      // partial, j-half 0
__device__ __align__(16) float  g_hp1[N_NODES * OUT_F];      // partial, j-half 1
__device__ float  g_z0[N_NODES];
__device__ float  g_z1[N_NODES];
__device__ float  g_s1[N_NODES];
__device__ float  g_s2[N_NODES];
__device__ unsigned int g_s2max_u = 0x007FFFFFu;             // encoded -inf (idempotent)
__device__ __align__(16) float2   g_A12[N_NODES];            // fp32 {A1, A2}
__device__ __align__(8)  uint32_t g_E12h[N_NODES];           // half2 {E1, E2}, both <= 1
__device__ float g_colsum[OUT_F];
__device__ float g_colsumsq[OUT_F];

// ---------------- helpers ----------------
__device__ __forceinline__ uint32_t smem_u32(const void* p) {
    uint32_t a;
    asm("{ .reg .u64 t; cvta.to.shared.u64 t, %1; cvt.u32.u64 %0, t; }" : "=r"(a) : "l"(p));
    return a;
}
__device__ __forceinline__ void cp16(uint32_t dst, const void* src) {
    asm volatile("cp.async.cg.shared.global [%0], [%1], 16;" :: "r"(dst), "l"(src) : "memory");
}
__device__ __forceinline__ void cp_commit() {
    asm volatile("cp.async.commit_group;" ::: "memory");
}
__device__ __forceinline__ void cp_wait0() {
    asm volatile("cp.async.wait_group 0;" ::: "memory");
}
__device__ __forceinline__ void cp_wait1() {
    asm volatile("cp.async.wait_group 1;" ::: "memory");
}
__device__ __forceinline__ void ldsm4(uint32_t* r, uint32_t addr) {
    asm volatile("ldmatrix.sync.aligned.m8n8.x4.shared.b16 {%0,%1,%2,%3}, [%4];"
                 : "=r"(r[0]), "=r"(r[1]), "=r"(r[2]), "=r"(r[3]) : "r"(addr));
}
__device__ __forceinline__ void mma16(float* c, const uint32_t* a, const uint32_t* b) {
    asm volatile(
        "mma.sync.aligned.m16n8k16.row.col.f32.f16.f16.f32 "
        "{%0,%1,%2,%3}, {%4,%5,%6,%7}, {%8,%9}, {%0,%1,%2,%3};"
        : "+f"(c[0]), "+f"(c[1]), "+f"(c[2]), "+f"(c[3])
        : "r"(a[0]), "r"(a[1]), "r"(a[2]), "r"(a[3]), "r"(b[0]), "r"(b[1]));
}
__device__ __forceinline__ float quat_sign(int rb, int cb) {
    float sgn = 1.f;
    if (cb == 0) { if (rb != 0) sgn = -1.f; }
    else if (rb == (cb % 3) + 1) sgn = -1.f;
    return sgn;
}

// ---------------- K0: transposed fp16 hamilton [c][k] ----------------
__global__ void k_ham16(const float* __restrict__ W) {
    int idx = blockIdx.x * blockDim.x + threadIdx.x;   // 0..65535
    int c = idx >> 9, k = idx & 511;
    int rb = k >> 7, rr = k & 127;
    int cb = c >> 5, cc = c & 31;
    int comp = rb ^ cb;
    g_ham16T[idx] = __float2half(quat_sign(rb, cb) * W[rr * 128 + comp * 32 + cc]);
}

// ---------------- K1: h = input @ hamilton via fp16 mma; emits g_h, g_hT16, s1/s2, s2max ----
// 128 CTAs x 256 thr (8 warps 2x4, warp tile 32x32). BM=64, BN=128, BK=64, 8 chunks.
__global__ void __launch_bounds__(256) k_h(const float* __restrict__ inp,
                                           const float* __restrict__ a_vec) {
    __shared__ __align__(16) char sm[64 * 132 * 4];    // 33792 B (overlaid)
    const uint32_t sb = smem_u32(sm);
    const uint32_t Ab = sb;                            // A: 64 x 144B = 9216
    const uint32_t Bb = sb + 9216;                     // B: 128 x 144B = 18432

    const int tid  = threadIdx.x;
    const int wid  = tid >> 5;
    const int lane = tid & 31;
    const int gid  = lane >> 2;
    const int t4   = lane & 3;
    const int i0   = blockIdx.x * 64;
    const int m0   = (wid >> 2) * 32;
    const int n0   = (wid & 3) * 32;

    const uint32_t aoffr = Ab + (uint32_t)((m0 + (lane & 7) + ((lane >> 3) & 1) * 8) * 144
                                           + ((lane >> 4) & 1) * 16);
    const uint32_t boffr = Bb + (uint32_t)((n0 + (lane & 7) + ((lane >> 4) & 1) * 8) * 144
                                           + ((lane >> 3) & 1) * 16);

    const int arow = tid >> 2;            // 0..63
    const int akq  = (tid & 3) * 16;      // 0/16/32/48

    float acc[2][4][4];
#pragma unroll
    for (int mb = 0; mb < 2; mb++)
#pragma unroll
        for (int nb = 0; nb < 4; nb++)
#pragma unroll
            for (int q = 0; q < 4; q++) acc[mb][nb][q] = 0.f;

    for (int kc = 0; kc < 8; kc++) {
        const int kb = kc * 64;
        // B tile via cp.async: ham16T[c][kb..kb+63]
#pragma unroll
        for (int q = 0; q < 4; q++) {
            int idx = q * 256 + tid;
            int c = idx >> 3, f8 = idx & 7;
            cp16(Bb + (uint32_t)(c * 144 + f8 * 16),
                 g_ham16T + c * IN_F + kb + f8 * 8);
        }
        cp_commit();
        // A tile: fp32 load + cvt + STS (16 halves per thread)
        {
            const float4* src = (const float4*)(inp + (size_t)(i0 + arow) * IN_F + kb + akq);
            float4 v0 = src[0], v1 = src[1], v2 = src[2], v3 = src[3];
            __half2 h0 = __floats2half2_rn(v0.x, v0.y);
            __half2 h1 = __floats2half2_rn(v0.z, v0.w);
            __half2 h2 = __floats2half2_rn(v1.x, v1.y);
            __half2 h3 = __floats2half2_rn(v1.z, v1.w);
            __half2 h4 = __floats2half2_rn(v2.x, v2.y);
            __half2 h5 = __floats2half2_rn(v2.z, v2.w);
            __half2 h6 = __floats2half2_rn(v3.x, v3.y);
            __half2 h7 = __floats2half2_rn(v3.z, v3.w);
            uint4 s0 = { *(uint32_t*)&h0, *(uint32_t*)&h1, *(uint32_t*)&h2, *(uint32_t*)&h3 };
            uint4 s1 = { *(uint32_t*)&h4, *(uint32_t*)&h5, *(uint32_t*)&h6, *(uint32_t*)&h7 };
            *(uint4*)(sm + (arow * 144 + akq * 2))      = s0;
            *(uint4*)(sm + (arow * 144 + akq * 2 + 16)) = s1;
        }
        cp_wait0();
        __syncthreads();
        // MMA
#pragma unroll
        for (int ks = 0; ks < 4; ks++) {
            uint32_t a0[4], a1[4], b01[4], b23[4];
            ldsm4(a0, aoffr + ks * 32);
            ldsm4(a1, aoffr + ks * 32 + 16 * 144);
            ldsm4(b01, boffr + ks * 32);
            ldsm4(b23, boffr + ks * 32 + 16 * 144);
            mma16(acc[0][0], a0, b01 + 0);
            mma16(acc[0][1], a0, b01 + 2);
            mma16(acc[0][2], a0, b23 + 0);
            mma16(acc[0][3], a0, b23 + 2);
            mma16(acc[1][0], a1, b01 + 0);
            mma16(acc[1][1], a1, b01 + 2);
            mma16(acc[1][2], a1, b23 + 0);
            mma16(acc[1][3], a1, b23 + 2);
        }
        __syncthreads();
    }

    // ---- epilogue: stage C (fp32) into smem, then emit everything ----
    float* C = (float*)sm;                 // 64 x 132 floats
#pragma unroll
    for (int mb = 0; mb < 2; mb++) {
        int r0 = m0 + mb * 16 + gid;
#pragma unroll
        for (int nb = 0; nb < 4; nb++) {
            int col = n0 + nb * 8 + t4 * 2;
            *(float2*)(C + r0 * 132 + col)       = make_float2(acc[mb][nb][0], acc[mb][nb][1]);
            *(float2*)(C + (r0 + 8) * 132 + col) = make_float2(acc[mb][nb][2], acc[mb][nb][3]);
        }
    }
    __syncthreads();

    // g_h (coalesced fp32)
    {
        int r = tid >> 2, cq = (tid & 3) * 32;
#pragma unroll
        for (int q = 0; q < 8; q++) {
            float4 v = *(float4*)(C + r * 132 + cq + q * 4);
            *(float4*)(g_h + (size_t)(i0 + r) * OUT_F + cq + q * 4) = v;
        }
    }
    // g_hT16 (transposed fp16)
    {
        int c = tid >> 1, j0 = (tid & 1) * 32;
        uint32_t hw[16];
#pragma unroll
        for (int q = 0; q < 16; q++) {
            float f0 = C[(j0 + 2 * q) * 132 + c];
            float f1 = C[(j0 + 2 * q + 1) * 132 + c];
            __half2 h = __floats2half2_rn(f0, f1);
            hw[q] = *(uint32_t*)&h;
        }
        uint4* dst = (uint4*)(g_hT16 + (size_t)c * N_NODES + i0 + j0);
#pragma unroll
        for (int q = 0; q < 4; q++)
            dst[q] = make_uint4(hw[q * 4], hw[q * 4 + 1], hw[q * 4 + 2], hw[q * 4 + 3]);
    }
    // s1/s2 per row + block s2max
    {
        float a1v[4], a2v[4];
#pragma unroll
        for (int q = 0; q < 4; q++) {
            a1v[q] = a_vec[lane + q * 32];
            a2v[q] = a_vec[OUT_F + lane + q * 32];
        }
        float m2 = -1e30f;
#pragma unroll
        for (int rr = 0; rr < 8; rr++) {
            int r = wid * 8 + rr;
            float s1 = 0.f, s2 = 0.f;
#pragma unroll
            for (int q = 0; q < 4; q++) {
                float hv = C[r * 132 + lane + q * 32];
                s1 = fmaf(hv, a1v[q], s1);
                s2 = fmaf(hv, a2v[q], s2);
            }
#pragma unroll
            for (int off = 16; off > 0; off >>= 1) {
                s1 += __shfl_xor_sync(0xffffffffu, s1, off);
                s2 += __shfl_xor_sync(0xffffffffu, s2, off);
            }
            if (lane == 0) {
                g_s1[i0 + r] = s1;
                g_s2[i0 + r] = s2;
                m2 = fmaxf(m2, s2);
            }
        }
        if (lane == 0) {
            uint32_t u = __float_as_uint(m2);
            u = (u & 0x80000000u) ? ~u : (u | 0x80000000u);
            atomicMax(&g_s2max_u, u);
        }
    }
}

// ---------------- K2: per-node exp factors (rescaled so all <= 1), + zero BN sums ----------------
__global__ void k_prep() {
    int i = blockIdx.x * blockDim.x + threadIdx.x;
    if (blockIdx.x == 0 && threadIdx.x < 128) {
        g_colsum[threadIdx.x] = 0.f; g_colsumsq[threadIdx.x] = 0.f;
    }
    uint32_t mu = g_s2max_u;
    float s2max = (mu & 0x80000000u) ? __uint_as_float(mu ^ 0x80000000u)
                                     : __uint_as_float(~mu);
    float s1 = g_s1[i], s2 = g_s2[i];
    float t = s1 + s2max;
    float m = (t > 0.f) ? t : ALPHA * t;
    float A1 = __expf(s1 + s2max - m);
    float A2 = __expf(ALPHA * (s1 + s2max) - m);
    float E1 = __expf(s2 - s2max);
    float E2 = __expf(ALPHA * (s2 - s2max));
    g_A12[i] = make_float2(A1, A2);
    __half2 e = __floats2half2_rn(E1, E2);
    g_E12h[i] = *(uint32_t*)&e;
}

// ---------------- K3: fused attention, fp16 mma.sync, 3-stage pipeline, split-j ----------------
#define PT_B 9216                         // 64 rows * 144 B
#define HS_B 18432                        // 128 rows * 144 B
#define H_OFF (2 * PT_B)                  // 18432
#define Z_OFF (H_OFF + 3 * HS_B)          // 73728
#define ATTN_SMEM (Z_OFF + 256)           // 73984
__global__ void __launch_bounds__(256, 2) k_attn(const int* __restrict__ adj) {
    extern __shared__ __align__(16) char smem[];
    const uint32_t sb = smem_u32(smem);
    float* zsh = (float*)(smem + Z_OFF);

    const int tid  = threadIdx.x;
    const int wid  = tid >> 5;
    const int lane = tid & 31;
    const int gid  = lane >> 2;
    const int t4   = lane & 3;
    const int bid  = blockIdx.x;
    const int i0   = (bid >> 1) * 64;
    const int jb0  = (bid & 1) * 4096;
    const int m0   = (wid >> 2) * 32;
    const int n0   = (wid & 3) * 32;

    if (tid < 64) zsh[tid] = 0.f;

    const int prow = tid >> 2;
    const int jl0  = (tid & 3) * 16;
    const float2 a12 = g_A12[i0 + prow];
    const float A1 = a12.x, A2 = a12.y;
    const int* arow = adj + (size_t)(i0 + prow) * N_NODES + jb0 + jl0;
    const uint32_t* esrc = g_E12h + jb0 + jl0;

    const uint32_t aoffr = (uint32_t)((m0 + (lane & 7) + ((lane >> 3) & 1) * 8) * 144
                                      + ((lane >> 4) & 1) * 16);
    const uint32_t boffr = (uint32_t)((n0 + (lane & 7) + ((lane >> 4) & 1) * 8) * 144
                                      + ((lane >> 3) & 1) * 16);

    float acc[2][4][4];
#pragma unroll
    for (int mb = 0; mb < 2; mb++)
#pragma unroll
        for (int nb = 0; nb < 4; nb++)
#pragma unroll
            for (int q = 0; q < 4; q++) acc[mb][nb][q] = 0.f;
    float zacc = 0.f;

#pragma unroll
    for (int s = 0; s < 2; s++) {
        uint32_t hdst = sb + H_OFF + (uint32_t)s * HS_B;
        const __half* src = g_hT16 + jb0 + s * 64;
#pragma unroll
        for (int q = 0; q < 4; q++) {
            int idx = q * 256 + tid;
            int c = idx >> 3, f8 = idx & 7;
            cp16(hdst + (uint32_t)(c * 144 + f8 * 16),
                 src + (size_t)c * N_NODES + f8 * 8);
        }
        cp_commit();
    }
    int4 av[4];
    uint4 ew[4];
#pragma unroll
    for (int g = 0; g < 4; g++) av[g] = *(const int4*)(arow + g * 4);
#pragma unroll
    for (int g = 0; g < 4; g++) ew[g] = *(const uint4*)(esrc + g * 4);

    for (int cc = 0; cc < 64; cc++) {
        const int p = cc & 1;
        const int hb = cc - (cc / 3) * 3;

        {
            char* PtB = smem + p * PT_B;
#pragma unroll
            for (int g = 0; g < 4; g++) {
                int4 a = av[g];
                float2 f0 = __half22float2(*(__half2*)&ew[g].x);
                float2 f1 = __half22float2(*(__half2*)&ew[g].y);
                float2 f2 = __half22float2(*(__half2*)&ew[g].z);
                float2 f3 = __half22float2(*(__half2*)&ew[g].w);
                float q0 = fmaxf(A1 * f0.x, A2 * f0.y);
                float q1 = fmaxf(A1 * f1.x, A2 * f1.y);
                float q2 = fmaxf(A1 * f2.x, A2 * f2.y);
                float q3 = fmaxf(A1 * f3.x, A2 * f3.y);
                if (a.x <= 0) q0 = 0.f;
                if (a.y <= 0) q1 = 0.f;
                if (a.z <= 0) q2 = 0.f;
                if (a.w <= 0) q3 = 0.f;
                __half2 h20 = __floats2half2_rn(q0, q1);
                __half2 h21 = __floats2half2_rn(q2, q3);
                float2 r0 = __half22float2(h20);
                float2 r1 = __half22float2(h21);
                zacc += (r0.x + r0.y) + (r1.x + r1.y);
                uint2 st = { *(uint32_t*)&h20, *(uint32_t*)&h21 };
                *(uint2*)(PtB + prow * 144 + (jl0 + g * 4) * 2) = st;
            }
        }

        if (cc < 63) {
            const int nj = (cc + 1) * 64;
#pragma unroll
            for (int g = 0; g < 4; g++) av[g] = *(const int4*)(arow + nj + g * 4);
#pragma unroll
            for (int g = 0; g < 4; g++) ew[g] = *(const uint4*)(esrc + nj + g * 4);
        }

        if (cc < 62) cp_wait1(); else cp_wait0();
        __syncthreads();

        if (cc + 2 < 64) {
            const int hb2 = (cc + 2) - ((cc + 2) / 3) * 3;
            uint32_t hdst = sb + H_OFF + (uint32_t)hb2 * HS_B;
            const __half* src = g_hT16 + jb0 + (cc + 2) * 64;
#pragma unroll
            for (int q = 0; q < 4; q++) {
                int idx = q * 256 + tid;
                int c = idx >> 3, f8 = idx & 7;
                cp16(hdst + (uint32_t)(c * 144 + f8 * 16),
                     src + (size_t)c * N_NODES + f8 * 8);
            }
            cp_commit();
        }

        {
            const uint32_t pa = sb + (uint32_t)p * PT_B + aoffr;
            const uint32_t pb = sb + H_OFF + (uint32_t)hb * HS_B + boffr;
#pragma unroll
            for (int ks = 0; ks < 4; ks++) {
                uint32_t a0[4], a1[4], b01[4], b23[4];
                ldsm4(a0, pa + ks * 32);
                ldsm4(a1, pa + ks * 32 + 16 * 144);
                ldsm4(b01, pb + ks * 32);
                ldsm4(b23, pb + ks * 32 + 16 * 144);
                mma16(acc[0][0], a0, b01 + 0);
                mma16(acc[0][1], a0, b01 + 2);
                mma16(acc[0][2], a0, b23 + 0);
                mma16(acc[0][3], a0, b23 + 2);
                mma16(acc[1][0], a1, b01 + 0);
                mma16(acc[1][1], a1, b01 + 2);
                mma16(acc[1][2], a1, b23 + 0);
                mma16(acc[1][3], a1, b23 + 2);
            }
        }
    }

    atomicAdd(&zsh[prow], zacc);
    __syncthreads();
    float* hpD = (bid & 1) ? g_hp1 : g_hp0;
    float* zD  = (bid & 1) ? g_z1  : g_z0;
    if (tid < 64) zD[i0 + tid] = zsh[tid];
#pragma unroll
    for (int mb = 0; mb < 2; mb++) {
        int r0 = m0 + mb * 16 + gid;
#pragma unroll
        for (int nb = 0; nb < 4; nb++) {
            int col = n0 + nb * 8 + t4 * 2;
            float2 v0 = {acc[mb][nb][0], acc[mb][nb][1]};
            float2 v1 = {acc[mb][nb][2], acc[mb][nb][3]};
            *(float2*)(hpD + (size_t)(i0 + r0) * OUT_F + col)     = v0;
            *(float2*)(hpD + (size_t)(i0 + r0 + 8) * OUT_F + col) = v1;
        }
    }
}

// ---------------- K4: merge halves, normalize, BN column stats ----------------
__global__ void k_stats() {
    int col = threadIdx.x & 127;
    int h = threadIdx.x >> 7;
    int r0 = blockIdx.x * 64;
    float s = 0.f, q = 0.f;
    for (int r = h; r < 64; r += 2) {
        int row = r0 + r;
        size_t idx = (size_t)row * OUT_F + col;
        float z = g_z0[row] + g_z1[row];
        float m = (g_hp0[idx] + g_hp1[idx]) / z;
        g_hp[idx] = m;
        s += m; q = fmaf(m, m, q);
    }
    atomicAdd(&g_colsum[col], s);
    atomicAdd(&g_colsumsq[col], q);
}

// ---------------- K5: BatchNorm + ELU ----------------
__global__ void k_bn(const float* __restrict__ gamma, const float* __restrict__ beta,
                     float* __restrict__ out) {
    int idx = blockIdx.x * blockDim.x + threadIdx.x;
    int col = idx & 127;
    const float invN = 1.0f / (float)N_NODES;
    float mean = g_colsum[col] * invN;
    float var  = g_colsumsq[col] * invN - mean * mean;
    float rstd = rsqrtf(var + BN_EPS);
    float v = (g_hp[idx] - mean) * rstd * gamma[col] + beta[col];
    out[idx] = (v > 0.f) ? v : expm1f(v);
}

// ---------------- launch ----------------
extern "C" void kernel_launch(void* const* d_in, const int* in_sizes, int n_in,
                              void* d_out, int out_size) {
    (void)in_sizes; (void)n_in; (void)out_size;
    const float* inp   = (const float*)d_in[0];
    const int*   adj   = (const int*)  d_in[1];
    const float* W     = (const float*)d_in[2];
    const float* a_vec = (const float*)d_in[3];
    const float* gamma = (const float*)d_in[4];
    const float* beta  = (const float*)d_in[5];
    float* out = (float*)d_out;

    static int smem_set = 0;
    if (!smem_set) {
        cudaFuncSetAttribute(k_attn, cudaFuncAttributeMaxDynamicSharedMemorySize, ATTN_SMEM);
        smem_set = 1;
    }

    k_ham16<<<256, 256>>>(W);
    k_h    <<<128, 256>>>(inp, a_vec);
    k_prep <<<32, 256>>>();
    k_attn <<<256, 256, ATTN_SMEM>>>(adj);     // launch #4 -> ncu captures this
    k_stats<<<128, 256>>>();
    k_bn   <<<4096, 256>>>(gamma, beta, out);
}